// round 2
// baseline (speedup 1.0000x reference)
#include <cuda_runtime.h>
#include <math.h>

// ---------------- problem constants ----------------
#define HW      768
#define C1      16
#define C2      32
#define C3      64
#define H2      384
#define H3      192
#define NG      96
#define NPATCH  9216          // 96*96
#define GPS     144
#define PADO    68
#define OUTPS   32

// stat offsets in the packed stat arrays
#define OFF1 0
#define OFF2 16
#define OFF3 48
#define NSTAT 112

// ---------------- device scratch (static, allowed) ----------------
__device__ float  g_f1[C1 * HW * HW];     // 37.7 MB
__device__ float  g_f2[C2 * H2 * H2];     // 18.9 MB
__device__ float  g_f3[C3 * H3 * H3];     //  9.4 MB
__device__ double g_sum[NSTAT];
__device__ double g_ssq[NSTAT];
__device__ float  g_mean[NSTAT];
__device__ float  g_rstd[NSTAT];
__device__ float  g_A[NPATCH * 4];
__device__ float  g_shift[2 * NPATCH];    // channel-major: [c][p]
__device__ float  g_trans[NPATCH * 6];

// ---------------- kernels ----------------

__global__ void k_zero_stats() {
    int i = threadIdx.x;
    if (i < NSTAT) { g_sum[i] = 0.0; g_ssq[i] = 0.0; }
}

// conv1: 1->16, 3x3, stride 1, pad 1, 768x768
__global__ void k_conv1(const float* __restrict__ img, const float* __restrict__ w) {
    __shared__ float sw[C1 * 9];
    int tid = threadIdx.y * 16 + threadIdx.x;
    if (tid < C1 * 9) sw[tid] = w[tid];
    __syncthreads();

    int x = blockIdx.x * 16 + threadIdx.x;
    int y = blockIdx.y * 16 + threadIdx.y;

    float v[9];
#pragma unroll
    for (int dy = 0; dy < 3; dy++)
#pragma unroll
        for (int dx = 0; dx < 3; dx++) {
            int iy = y + dy - 1, ix = x + dx - 1;
            v[dy * 3 + dx] = ((unsigned)iy < HW && (unsigned)ix < HW)
                                 ? img[iy * HW + ix] : 0.f;
        }
#pragma unroll
    for (int c = 0; c < C1; c++) {
        float a = 0.f;
#pragma unroll
        for (int k = 0; k < 9; k++) a += v[k] * sw[c * 9 + k];
        g_f1[(size_t)c * HW * HW + (size_t)y * HW + x] = a;
    }
}

// per-channel sum / sumsq reduction (fp64 accumulate)
template <int STAGE>
__global__ void k_stats() {
    constexpr int hw  = (STAGE == 1) ? HW * HW : (STAGE == 2) ? H2 * H2 : H3 * H3;
    constexpr int off = (STAGE == 1) ? OFF1 : (STAGE == 2) ? OFF2 : OFF3;
    const float* base = (STAGE == 1) ? g_f1 : (STAGE == 2) ? g_f2 : g_f3;

    int c = blockIdx.x;
    const float* p = base + (size_t)c * hw;
    double s = 0.0, q = 0.0;
    for (int i = blockIdx.y * blockDim.x + threadIdx.x; i < hw;
         i += gridDim.y * blockDim.x) {
        double v = (double)p[i];
        s += v; q += v * v;
    }
    __shared__ double ss[256], sq[256];
    ss[threadIdx.x] = s; sq[threadIdx.x] = q;
    __syncthreads();
    for (int st = 128; st > 0; st >>= 1) {
        if (threadIdx.x < st) {
            ss[threadIdx.x] += ss[threadIdx.x + st];
            sq[threadIdx.x] += sq[threadIdx.x + st];
        }
        __syncthreads();
    }
    if (threadIdx.x == 0) {
        atomicAdd(&g_sum[off + c], ss[0]);
        atomicAdd(&g_ssq[off + c], sq[0]);
    }
}

__global__ void k_finalize(int off, int nc, int hw) {
    int c = threadIdx.x;
    if (c < nc) {
        double m = g_sum[off + c] / hw;
        double v = g_ssq[off + c] / hw - m * m;
        g_mean[off + c] = (float)m;
        g_rstd[off + c] = (float)rsqrt(v + 1e-5);
    }
}

// stride-2 3x3 conv with fused BN+ReLU on the input
// STAGE 2: 16->32, 768->384 ; STAGE 3: 32->64, 384->192
// NOTE: out-of-bounds halo must be literal 0 (reference pads the normalized
// feature map with zeros), NOT bn_relu(0).
template <int STAGE>
__global__ void k_conv_s2(const float* __restrict__ w) {
    constexpr int CIN  = (STAGE == 2) ? C1 : C2;
    constexpr int COUT = (STAGE == 2) ? C2 : C3;
    constexpr int HIN  = (STAGE == 2) ? HW : H2;
    constexpr int HOUT = (STAGE == 2) ? H2 : H3;
    constexpr int soff = (STAGE == 2) ? OFF1 : OFF2;
    const float* in  = (STAGE == 2) ? g_f1 : g_f2;
    float*       out = (STAGE == 2) ? g_f2 : g_f3;

    __shared__ float tile[33 * 33];
    __shared__ float sw[COUT * 9];
    __shared__ float smean[CIN], srstd[CIN];

    int tid = threadIdx.y * 16 + threadIdx.x;
    if (tid < CIN) {
        smean[tid] = g_mean[soff + tid];
        srstd[tid] = g_rstd[soff + tid];
    }

    int ox  = blockIdx.x * 16 + threadIdx.x;
    int oy  = blockIdx.y * 16 + threadIdx.y;
    int ibx = blockIdx.x * 32 - 1;
    int iby = blockIdx.y * 32 - 1;

    float acc[COUT];
#pragma unroll
    for (int o = 0; o < COUT; o++) acc[o] = 0.f;

    for (int c = 0; c < CIN; c++) {
        __syncthreads();
        float m = smean[c], r = srstd[c];
        const float* ic = in + (size_t)c * HIN * HIN;
        for (int i = tid; i < 33 * 33; i += 256) {
            int rr = i / 33, cc = i - rr * 33;
            int iy = iby + rr, ix = ibx + cc;
            float t = 0.f;
            if ((unsigned)iy < HIN && (unsigned)ix < HIN) {
                float v = ic[(size_t)iy * HIN + ix];
                t = fmaxf((v - m) * r, 0.f);
            }
            tile[i] = t;
        }
        for (int i = tid; i < COUT * 9; i += 256)
            sw[i] = w[(i / 9) * (CIN * 9) + c * 9 + (i % 9)];
        __syncthreads();

        float v[9];
#pragma unroll
        for (int kh = 0; kh < 3; kh++)
#pragma unroll
            for (int kw = 0; kw < 3; kw++)
                v[kh * 3 + kw] =
                    tile[(2 * threadIdx.y + kh) * 33 + 2 * threadIdx.x + kw];
#pragma unroll
        for (int o = 0; o < COUT; o++) {
            float a = acc[o];
#pragma unroll
            for (int k = 0; k < 9; k++) a += v[k] * sw[o * 9 + k];
            acc[o] = a;
        }
    }
#pragma unroll
    for (int o = 0; o < COUT; o++)
        out[(size_t)o * HOUT * HOUT + (size_t)oy * HOUT + ox] = acc[o];
}

// heads: 2x2 stride-2 convs over bnrelu(f3), 6 output channels total
__global__ void k_heads(const float* __restrict__ pw, const float* __restrict__ pb,
                        const float* __restrict__ tw, const float* __restrict__ tb,
                        const float* __restrict__ shw, const float* __restrict__ shb,
                        const float* __restrict__ scw, const float* __restrict__ scb,
                        const float* __restrict__ tiw, const float* __restrict__ tib) {
    int p = blockIdx.x * blockDim.x + threadIdx.x;
    if (p >= NPATCH) return;
    int gx = p % NG, gy = p / NG;

    float ap = 0, at = 0, as0 = 0, as1 = 0, asc = 0, ati = 0;
    for (int c = 0; c < C3; c++) {
        float m = g_mean[OFF3 + c], r = g_rstd[OFF3 + c];
        const float* fc = g_f3 + (size_t)c * H3 * H3 + (size_t)(2 * gy) * H3 + 2 * gx;
#pragma unroll
        for (int kh = 0; kh < 2; kh++)
#pragma unroll
            for (int kw = 0; kw < 2; kw++) {
                float v = fmaxf((fc[kh * H3 + kw] - m) * r, 0.f);
                int wi = c * 4 + kh * 2 + kw;
                ap  += v * pw[wi];
                at  += v * tw[wi];
                as0 += v * shw[wi];
                as1 += v * shw[256 + wi];
                asc += v * scw[wi];
                ati += v * tiw[wi];
            }
    }
    float psi = 3.14159f * tanhf(ap + pb[0]);
    float th  = 3.14159f * tanhf(at + tb[0]);
    float s0  = 0.2f * tanhf(as0 + shb[0]);
    float s1  = 0.2f * tanhf(as1 + shb[1]);
    float sc  = fminf(fmaxf(1.f + 0.25f * tanhf(asc + scb[0]), 0.8f), 1.25f);
    float ti  = fminf(fmaxf(1.f + 0.8f  * tanhf(ati + tib[0]), 1.0f), 1.8f);

    float cp = cosf(psi), sp = sinf(psi);
    float ct = cosf(th),  st = sinf(th);
    float M00 = ti * ct, M01 = -ti * st;
    float M10 = st / ti, M11 = ct / ti;
    g_A[p * 4 + 0] = sc * (cp * M00 - sp * M10);
    g_A[p * 4 + 1] = sc * (cp * M01 - sp * M11);
    g_A[p * 4 + 2] = sc * (sp * M00 + cp * M10);
    g_A[p * 4 + 3] = sc * (sp * M01 + cp * M11);
    g_shift[p]          = s0;   // channel 0, pixel p
    g_shift[NPATCH + p] = s1;   // channel 1, pixel p
}

// assemble transform (with the reference's cross-channel shift re-index) + aff
__global__ void k_assemble(float* __restrict__ out) {
    int n = blockIdx.x * blockDim.x + threadIdx.x;
    if (n >= NPATCH) return;
    float t0 = g_A[n * 4 + 0], t1 = g_A[n * 4 + 1];
    float t3 = g_A[n * 4 + 2], t4 = g_A[n * 4 + 3];
    // reference does shift.reshape(-1,2,1) on [2][9216] flat data:
    float t2 = g_shift[2 * n];
    float t5 = g_shift[2 * n + 1];
    g_trans[n * 6 + 0] = t0; g_trans[n * 6 + 1] = t1; g_trans[n * 6 + 2] = t2;
    g_trans[n * 6 + 3] = t3; g_trans[n * 6 + 4] = t4; g_trans[n * 6 + 5] = t5;

    float cx = 4.f + 8.f * (float)(n % NG);
    float cy = 4.f + 8.f * (float)(n / NG);
    float* a = out + (size_t)NPATCH * 1024 + (size_t)n * 6;
    a[0] = 32.f * t0; a[1] = 32.f * t1; a[2] = cx + 32.f * t2;
    a[3] = 32.f * t3; a[4] = 32.f * t4; a[5] = cy + 32.f * t5;
}

// bilinear grid sample; one block per patch, 1024 threads = 32x32 pixels
__global__ void k_sample(const float* __restrict__ img, float* __restrict__ out) {
    int n = blockIdx.x;
    __shared__ float t[6];
    if (threadIdx.x < 6) t[threadIdx.x] = g_trans[n * 6 + threadIdx.x];
    __syncthreads();

    int w = threadIdx.x & 31, h = threadIdx.x >> 5;
    float X = ((float)w + 0.5f) * (2.f / 32.f) - 1.f;
    float Y = ((float)h + 0.5f) * (2.f / 32.f) - 1.f;
    float gx = (X * t[0] + Y * t[1] + t[2]) / 4.5f;
    float gy = (X * t[3] + Y * t[4] + t[5]) / 4.5f;
    float ix = ((gx + 1.f) * 144.f - 1.f) * 0.5f;
    float iy = ((gy + 1.f) * 144.f - 1.f) * 0.5f;
    float x0f = floorf(ix), y0f = floorf(iy);
    float wx = ix - x0f, wy = iy - y0f;
    int x0 = (int)x0f, y0 = (int)y0f;
    int bx = (n % NG) * 8 - PADO;
    int by = (n / NG) * 8 - PADO;

    auto g = [&](int yy, int xx) -> float {
        if ((unsigned)yy >= GPS || (unsigned)xx >= GPS) return 0.f;
        int ir = by + yy, ic = bx + xx;
        if ((unsigned)ir >= HW || (unsigned)ic >= HW) return 0.f;
        return img[(size_t)ir * HW + ic];
    };
    float v = (1.f - wy) * ((1.f - wx) * g(y0, x0)     + wx * g(y0, x0 + 1)) +
              wy        * ((1.f - wx) * g(y0 + 1, x0) + wx * g(y0 + 1, x0 + 1));
    out[(size_t)n * 1024 + threadIdx.x] = v;
}

// ---------------- launch ----------------
extern "C" void kernel_launch(void* const* d_in, const int* in_sizes, int n_in,
                              void* d_out, int out_size) {
    const float* img = (const float*)d_in[0];
    const float* w1  = (const float*)d_in[1];
    const float* w2  = (const float*)d_in[2];
    const float* w3  = (const float*)d_in[3];
    const float* pw  = (const float*)d_in[4];
    const float* pb  = (const float*)d_in[5];
    const float* tw  = (const float*)d_in[6];
    const float* tb  = (const float*)d_in[7];
    const float* shw = (const float*)d_in[8];
    const float* shb = (const float*)d_in[9];
    const float* scw = (const float*)d_in[10];
    const float* scb = (const float*)d_in[11];
    const float* tiw = (const float*)d_in[12];
    const float* tib = (const float*)d_in[13];
    float* out = (float*)d_out;

    k_zero_stats<<<1, 128>>>();
    k_conv1<<<dim3(48, 48), dim3(16, 16)>>>(img, w1);
    k_stats<1><<<dim3(16, 64), 256>>>();
    k_finalize<<<1, 16>>>(OFF1, 16, HW * HW);
    k_conv_s2<2><<<dim3(24, 24), dim3(16, 16)>>>(w2);
    k_stats<2><<<dim3(32, 32), 256>>>();
    k_finalize<<<1, 32>>>(OFF2, 32, H2 * H2);
    k_conv_s2<3><<<dim3(12, 12), dim3(16, 16)>>>(w3);
    k_stats<3><<<dim3(64, 16), 256>>>();
    k_finalize<<<1, 64>>>(OFF3, 64, H3 * H3);
    k_heads<<<36, 256>>>(pw, pb, tw, tb, shw, shb, scw, scb, tiw, tib);
    k_assemble<<<36, 256>>>(out);
    k_sample<<<NPATCH, 1024>>>(img, out);
}

// round 3
// speedup vs baseline: 1.1705x; 1.1705x over previous
#include <cuda_runtime.h>
#include <math.h>

// ---------------- constants ----------------
#define HW      768
#define C1      16
#define C2      32
#define C3      64
#define H2      384
#define H3      192
#define NG      96
#define NPATCH  9216
#define GPS     144
#define PADO    68
#define SLOTS   32

// ---------------- device scratch ----------------
__device__ double g_sum1[C1 * SLOTS], g_ssq1[C1 * SLOTS];
__device__ double g_sum2[C2 * SLOTS], g_ssq2[C2 * SLOTS];
__device__ double g_sum3[C3 * SLOTS], g_ssq3[C3 * SLOTS];
__device__ float  g_f2[C2 * H2 * H2];
__device__ float  g_f3[C3 * H3 * H3];
__device__ float  g_A[NPATCH * 4];
__device__ float  g_shift[2 * NPATCH];
__device__ float  g_trans[NPATCH * 6];

// ---------------- zero stats (replayed each graph launch) ----------------
__global__ void k_zero_stats() {
    int t = threadIdx.x;
    for (int i = t; i < C1 * SLOTS; i += 1024) { g_sum1[i] = 0; g_ssq1[i] = 0; }
    for (int i = t; i < C2 * SLOTS; i += 1024) { g_sum2[i] = 0; g_ssq2[i] = 0; }
    for (int i = t; i < C3 * SLOTS; i += 1024) { g_sum3[i] = 0; g_ssq3[i] = 0; }
}

// ---------------- K1: conv1 stats only (no f1 store) ----------------
__global__ __launch_bounds__(256) void k_conv1s(const float* __restrict__ img,
                                                const float* __restrict__ w1) {
    __shared__ float sw[C1 * 9];
    __shared__ float sred[8 * C1], qred[8 * C1];
    int tid = threadIdx.x, tx = tid & 15, ty = tid >> 4;
    if (tid < C1 * 9) sw[tid] = w1[tid];
    __syncthreads();

    int x = blockIdx.x * 16 + tx;
    int y = blockIdx.y * 16 + ty;

    float v[9];
#pragma unroll
    for (int dy = 0; dy < 3; dy++)
#pragma unroll
        for (int dx = 0; dx < 3; dx++) {
            int iy = y + dy - 1, ix = x + dx - 1;
            v[dy * 3 + dx] = ((unsigned)iy < HW && (unsigned)ix < HW)
                                 ? img[iy * HW + ix] : 0.f;
        }
    float val[C1];
#pragma unroll
    for (int c = 0; c < C1; c++) {
        float a = 0.f;
#pragma unroll
        for (int k = 0; k < 9; k++) a += v[k] * sw[c * 9 + k];
        val[c] = a;
    }
    int lane = tid & 31, warp = tid >> 5;
    for (int c = 0; c < C1; c++) {
        float s = val[c], q = val[c] * val[c];
        for (int d = 16; d; d >>= 1) {
            s += __shfl_xor_sync(~0u, s, d);
            q += __shfl_xor_sync(~0u, q, d);
        }
        if (lane == 0) { sred[warp * C1 + c] = s; qred[warp * C1 + c] = q; }
    }
    __syncthreads();
    if (tid < C1) {
        float s = 0, q = 0;
        for (int w8 = 0; w8 < 8; w8++) { s += sred[w8 * C1 + tid]; q += qred[w8 * C1 + tid]; }
        int slot = (blockIdx.y * gridDim.x + blockIdx.x) & (SLOTS - 1);
        atomicAdd(&g_sum1[tid * SLOTS + slot], (double)s);
        atomicAdd(&g_ssq1[tid * SLOTS + slot], (double)q);
    }
}

// ---------------- K2: fused conv1 + bn1 + conv2 + stats2 ----------------
// block: 256 threads; output tile 32(x) x 16(y) of f2; grid (12,24)
__global__ __launch_bounds__(256, 2) void k_conv2f(const float* __restrict__ img,
                                                   const float* __restrict__ w1,
                                                   const float* __restrict__ w2) {
    __shared__ float simg[35 * 67];
    __shared__ float sf1[33 * 65];
    __shared__ float sw1[C1 * 9];
    __shared__ float sw2[C2 * 9];
    __shared__ float sm1[C1], sr1[C1];
    __shared__ float sred[8 * C2], qred[8 * C2];

    int tid = threadIdx.x, tx = tid & 15, ty = tid >> 4;
    int ibx = 64 * blockIdx.x - 1;   // f1-tile origin (x)
    int iby = 32 * blockIdx.y - 1;   // f1-tile origin (y)

    for (int i = tid; i < 35 * 67; i += 256) {
        int r = i / 67, c = i - r * 67;
        int yy = iby - 1 + r, xx = ibx - 1 + c;
        simg[i] = ((unsigned)yy < HW && (unsigned)xx < HW) ? img[yy * HW + xx] : 0.f;
    }
    if (tid < C1 * 9) sw1[tid] = w1[tid];
    if (tid < C1) {
        double s = 0, q = 0;
        for (int j = 0; j < SLOTS; j++) { s += g_sum1[tid * SLOTS + j]; q += g_ssq1[tid * SLOTS + j]; }
        double m = s / (double)(HW * HW);
        double v = q / (double)(HW * HW) - m * m;
        sm1[tid] = (float)m;
        sr1[tid] = (float)rsqrt(v + 1e-5);
    }

    float acc0[C2], acc1[C2];
#pragma unroll
    for (int o = 0; o < C2; o++) { acc0[o] = 0.f; acc1[o] = 0.f; }

    for (int c1 = 0; c1 < C1; c1++) {
        __syncthreads();          // protect prev sf1/sw2 readers (also covers init loads)
        float m = sm1[c1], rs = sr1[c1];
        const float* wp = &sw1[c1 * 9];
        for (int i = tid; i < 33 * 65; i += 256) {
            int rr = i / 65, cc = i - rr * 65;
            int fy = iby + rr, fx = ibx + cc;
            float t = 0.f;
            if ((unsigned)fy < HW && (unsigned)fx < HW) {
                float a = 0.f;
#pragma unroll
                for (int dy = 0; dy < 3; dy++)
#pragma unroll
                    for (int dx = 0; dx < 3; dx++)
                        a += simg[(rr + dy) * 67 + cc + dx] * wp[dy * 3 + dx];
                t = fmaxf((a - m) * rs, 0.f);
            }
            sf1[i] = t;
        }
        for (int i = tid; i < C2 * 9; i += 256)
            sw2[i] = w2[(i / 9) * (C1 * 9) + c1 * 9 + (i % 9)];
        __syncthreads();

        float v0[9], v1[9];
#pragma unroll
        for (int kh = 0; kh < 3; kh++)
#pragma unroll
            for (int kw = 0; kw < 3; kw++) {
                v0[kh * 3 + kw] = sf1[(2 * ty + kh) * 65 + 2 * tx + kw];
                v1[kh * 3 + kw] = sf1[(2 * ty + kh) * 65 + 2 * tx + 32 + kw];
            }
#pragma unroll
        for (int o = 0; o < C2; o++) {
            float a0 = acc0[o], a1 = acc1[o];
#pragma unroll
            for (int k = 0; k < 9; k++) {
                float f = sw2[o * 9 + k];
                a0 += v0[k] * f;
                a1 += v1[k] * f;
            }
            acc0[o] = a0; acc1[o] = a1;
        }
    }

    int oy = blockIdx.y * 16 + ty, ox = blockIdx.x * 32 + tx;
#pragma unroll
    for (int o = 0; o < C2; o++) {
        g_f2[(size_t)o * H2 * H2 + (size_t)oy * H2 + ox]      = acc0[o];
        g_f2[(size_t)o * H2 * H2 + (size_t)oy * H2 + ox + 16] = acc1[o];
    }
    int lane = tid & 31, warp = tid >> 5;
    for (int o = 0; o < C2; o++) {
        float s = acc0[o] + acc1[o];
        float q = acc0[o] * acc0[o] + acc1[o] * acc1[o];
        for (int d = 16; d; d >>= 1) {
            s += __shfl_xor_sync(~0u, s, d);
            q += __shfl_xor_sync(~0u, q, d);
        }
        if (lane == 0) { sred[warp * C2 + o] = s; qred[warp * C2 + o] = q; }
    }
    __syncthreads();
    if (tid < C2) {
        float s = 0, q = 0;
        for (int w8 = 0; w8 < 8; w8++) { s += sred[w8 * C2 + tid]; q += qred[w8 * C2 + tid]; }
        int slot = (blockIdx.y * gridDim.x + blockIdx.x) & (SLOTS - 1);
        atomicAdd(&g_sum2[tid * SLOTS + slot], (double)s);
        atomicAdd(&g_ssq2[tid * SLOTS + slot], (double)q);
    }
}

// ---------------- K3: bn2 + conv3 + stats3 ----------------
// grid (6,12,4): output tile 32(x) x 16(y), 16 output channels per z-group
__global__ __launch_bounds__(256, 2) void k_conv3f(const float* __restrict__ w3) {
    __shared__ float sf2[33 * 65];
    __shared__ float sw3[16 * 9];
    __shared__ float sm2[C2], sr2[C2];
    __shared__ float sred[8 * 16], qred[8 * 16];

    int tid = threadIdx.x, tx = tid & 15, ty = tid >> 4;
    int ibx = 64 * blockIdx.x - 1;
    int iby = 32 * blockIdx.y - 1;
    int obase = blockIdx.z * 16;

    if (tid < C2) {
        double s = 0, q = 0;
        for (int j = 0; j < SLOTS; j++) { s += g_sum2[tid * SLOTS + j]; q += g_ssq2[tid * SLOTS + j]; }
        double m = s / (double)(H2 * H2);
        double v = q / (double)(H2 * H2) - m * m;
        sm2[tid] = (float)m;
        sr2[tid] = (float)rsqrt(v + 1e-5);
    }

    float acc0[16], acc1[16];
#pragma unroll
    for (int o = 0; o < 16; o++) { acc0[o] = 0.f; acc1[o] = 0.f; }

    for (int c = 0; c < C2; c++) {
        __syncthreads();
        float m = sm2[c], rs = sr2[c];
        const float* ic = g_f2 + (size_t)c * H2 * H2;
        for (int i = tid; i < 33 * 65; i += 256) {
            int rr = i / 65, cc = i - rr * 65;
            int fy = iby + rr, fx = ibx + cc;
            float t = 0.f;
            if ((unsigned)fy < H2 && (unsigned)fx < H2)
                t = fmaxf((ic[(size_t)fy * H2 + fx] - m) * rs, 0.f);
            sf2[i] = t;
        }
        if (tid < 16 * 9)
            sw3[tid] = w3[(obase + tid / 9) * (C2 * 9) + c * 9 + (tid % 9)];
        __syncthreads();

        float v0[9], v1[9];
#pragma unroll
        for (int kh = 0; kh < 3; kh++)
#pragma unroll
            for (int kw = 0; kw < 3; kw++) {
                v0[kh * 3 + kw] = sf2[(2 * ty + kh) * 65 + 2 * tx + kw];
                v1[kh * 3 + kw] = sf2[(2 * ty + kh) * 65 + 2 * tx + 32 + kw];
            }
#pragma unroll
        for (int o = 0; o < 16; o++) {
            float a0 = acc0[o], a1 = acc1[o];
#pragma unroll
            for (int k = 0; k < 9; k++) {
                float f = sw3[o * 9 + k];
                a0 += v0[k] * f;
                a1 += v1[k] * f;
            }
            acc0[o] = a0; acc1[o] = a1;
        }
    }

    int oy = blockIdx.y * 16 + ty, ox = blockIdx.x * 32 + tx;
#pragma unroll
    for (int o = 0; o < 16; o++) {
        g_f3[(size_t)(obase + o) * H3 * H3 + (size_t)oy * H3 + ox]      = acc0[o];
        g_f3[(size_t)(obase + o) * H3 * H3 + (size_t)oy * H3 + ox + 16] = acc1[o];
    }
    int lane = tid & 31, warp = tid >> 5;
    for (int o = 0; o < 16; o++) {
        float s = acc0[o] + acc1[o];
        float q = acc0[o] * acc0[o] + acc1[o] * acc1[o];
        for (int d = 16; d; d >>= 1) {
            s += __shfl_xor_sync(~0u, s, d);
            q += __shfl_xor_sync(~0u, q, d);
        }
        if (lane == 0) { sred[warp * 16 + o] = s; qred[warp * 16 + o] = q; }
    }
    __syncthreads();
    if (tid < 16) {
        float s = 0, q = 0;
        for (int w8 = 0; w8 < 8; w8++) { s += sred[w8 * 16 + tid]; q += qred[w8 * 16 + tid]; }
        int slot = ((blockIdx.z * gridDim.y + blockIdx.y) * gridDim.x + blockIdx.x) & (SLOTS - 1);
        atomicAdd(&g_sum3[(obase + tid) * SLOTS + slot], (double)s);
        atomicAdd(&g_ssq3[(obase + tid) * SLOTS + slot], (double)q);
    }
}

// ---------------- heads ----------------
__global__ __launch_bounds__(256) void k_heads(
    const float* __restrict__ pw, const float* __restrict__ pb,
    const float* __restrict__ tw, const float* __restrict__ tb,
    const float* __restrict__ shw, const float* __restrict__ shb,
    const float* __restrict__ scw, const float* __restrict__ scb,
    const float* __restrict__ tiw, const float* __restrict__ tib) {
    __shared__ float sm3[C3], sr3[C3];
    int tid = threadIdx.x;
    if (tid < C3) {
        double s = 0, q = 0;
        for (int j = 0; j < SLOTS; j++) { s += g_sum3[tid * SLOTS + j]; q += g_ssq3[tid * SLOTS + j]; }
        double m = s / (double)(H3 * H3);
        double v = q / (double)(H3 * H3) - m * m;
        sm3[tid] = (float)m;
        sr3[tid] = (float)rsqrt(v + 1e-5);
    }
    __syncthreads();

    int p = blockIdx.x * blockDim.x + tid;
    if (p >= NPATCH) return;
    int gx = p % NG, gy = p / NG;

    float ap = 0, at = 0, as0 = 0, as1 = 0, asc = 0, ati = 0;
    for (int c = 0; c < C3; c++) {
        float m = sm3[c], r = sr3[c];
        const float* fc = g_f3 + (size_t)c * H3 * H3 + (size_t)(2 * gy) * H3 + 2 * gx;
#pragma unroll
        for (int kh = 0; kh < 2; kh++)
#pragma unroll
            for (int kw = 0; kw < 2; kw++) {
                float v = fmaxf((fc[kh * H3 + kw] - m) * r, 0.f);
                int wi = c * 4 + kh * 2 + kw;
                ap  += v * pw[wi];
                at  += v * tw[wi];
                as0 += v * shw[wi];
                as1 += v * shw[256 + wi];
                asc += v * scw[wi];
                ati += v * tiw[wi];
            }
    }
    float psi = 3.14159f * tanhf(ap + pb[0]);
    float th  = 3.14159f * tanhf(at + tb[0]);
    float s0  = 0.2f * tanhf(as0 + shb[0]);
    float s1  = 0.2f * tanhf(as1 + shb[1]);
    float sc  = fminf(fmaxf(1.f + 0.25f * tanhf(asc + scb[0]), 0.8f), 1.25f);
    float ti  = fminf(fmaxf(1.f + 0.8f  * tanhf(ati + tib[0]), 1.0f), 1.8f);

    float cp = cosf(psi), sp = sinf(psi);
    float ct = cosf(th),  st = sinf(th);
    float M00 = ti * ct, M01 = -ti * st;
    float M10 = st / ti, M11 = ct / ti;
    g_A[p * 4 + 0] = sc * (cp * M00 - sp * M10);
    g_A[p * 4 + 1] = sc * (cp * M01 - sp * M11);
    g_A[p * 4 + 2] = sc * (sp * M00 + cp * M10);
    g_A[p * 4 + 3] = sc * (sp * M01 + cp * M11);
    g_shift[p]          = s0;
    g_shift[NPATCH + p] = s1;
}

// ---------------- assemble (shift cross-channel reindex) + aff ----------------
__global__ void k_assemble(float* __restrict__ out) {
    int n = blockIdx.x * blockDim.x + threadIdx.x;
    if (n >= NPATCH) return;
    float t0 = g_A[n * 4 + 0], t1 = g_A[n * 4 + 1];
    float t3 = g_A[n * 4 + 2], t4 = g_A[n * 4 + 3];
    float t2 = g_shift[2 * n];
    float t5 = g_shift[2 * n + 1];
    g_trans[n * 6 + 0] = t0; g_trans[n * 6 + 1] = t1; g_trans[n * 6 + 2] = t2;
    g_trans[n * 6 + 3] = t3; g_trans[n * 6 + 4] = t4; g_trans[n * 6 + 5] = t5;

    float cx = 4.f + 8.f * (float)(n % NG);
    float cy = 4.f + 8.f * (float)(n / NG);
    float* a = out + (size_t)NPATCH * 1024 + (size_t)n * 6;
    a[0] = 32.f * t0; a[1] = 32.f * t1; a[2] = cx + 32.f * t2;
    a[3] = 32.f * t3; a[4] = 32.f * t4; a[5] = cy + 32.f * t5;
}

// ---------------- bilinear sampler ----------------
__global__ __launch_bounds__(1024) void k_sample(const float* __restrict__ img,
                                                 float* __restrict__ out) {
    int n = blockIdx.x;
    __shared__ float t[6];
    if (threadIdx.x < 6) t[threadIdx.x] = g_trans[n * 6 + threadIdx.x];
    __syncthreads();

    int w = threadIdx.x & 31, h = threadIdx.x >> 5;
    float X = ((float)w + 0.5f) * (2.f / 32.f) - 1.f;
    float Y = ((float)h + 0.5f) * (2.f / 32.f) - 1.f;
    float gx = (X * t[0] + Y * t[1] + t[2]) / 4.5f;
    float gy = (X * t[3] + Y * t[4] + t[5]) / 4.5f;
    float ix = ((gx + 1.f) * 144.f - 1.f) * 0.5f;
    float iy = ((gy + 1.f) * 144.f - 1.f) * 0.5f;
    float x0f = floorf(ix), y0f = floorf(iy);
    float wx = ix - x0f, wy = iy - y0f;
    int x0 = (int)x0f, y0 = (int)y0f;
    int bx = (n % NG) * 8 - PADO;
    int by = (n / NG) * 8 - PADO;

    auto g = [&](int yy, int xx) -> float {
        if ((unsigned)yy >= GPS || (unsigned)xx >= GPS) return 0.f;
        int ir = by + yy, ic = bx + xx;
        if ((unsigned)ir >= HW || (unsigned)ic >= HW) return 0.f;
        return img[(size_t)ir * HW + ic];
    };
    float v = (1.f - wy) * ((1.f - wx) * g(y0, x0)     + wx * g(y0, x0 + 1)) +
              wy        * ((1.f - wx) * g(y0 + 1, x0) + wx * g(y0 + 1, x0 + 1));
    out[(size_t)n * 1024 + threadIdx.x] = v;
}

// ---------------- launch ----------------
extern "C" void kernel_launch(void* const* d_in, const int* in_sizes, int n_in,
                              void* d_out, int out_size) {
    const float* img = (const float*)d_in[0];
    const float* w1  = (const float*)d_in[1];
    const float* w2  = (const float*)d_in[2];
    const float* w3  = (const float*)d_in[3];
    const float* pw  = (const float*)d_in[4];
    const float* pb  = (const float*)d_in[5];
    const float* tw  = (const float*)d_in[6];
    const float* tb  = (const float*)d_in[7];
    const float* shw = (const float*)d_in[8];
    const float* shb = (const float*)d_in[9];
    const float* scw = (const float*)d_in[10];
    const float* scb = (const float*)d_in[11];
    const float* tiw = (const float*)d_in[12];
    const float* tib = (const float*)d_in[13];
    float* out = (float*)d_out;

    k_zero_stats<<<1, 1024>>>();
    k_conv1s<<<dim3(48, 48), 256>>>(img, w1);
    k_conv2f<<<dim3(12, 24), 256>>>(img, w1, w2);
    k_conv3f<<<dim3(6, 12, 4), 256>>>(w3);
    k_heads<<<36, 256>>>(pw, pb, tw, tb, shw, shb, scw, scb, tiw, tib);
    k_assemble<<<36, 256>>>(out);
    k_sample<<<NPATCH, 1024>>>(img, out);
}

// round 4
// speedup vs baseline: 1.1850x; 1.0124x over previous
#include <cuda_runtime.h>
#include <math.h>

// ---------------- constants ----------------
#define HW      768
#define C1      16
#define C2      32
#define C3      64
#define H2      384
#define H3      192
#define NG      96
#define NPATCH  9216
#define GPS     144
#define PADO    68
#define SLOTS   32

// ---------------- device scratch ----------------
__device__ double g_sum1[C1 * SLOTS], g_ssq1[C1 * SLOTS];
__device__ double g_sum2[C2 * SLOTS], g_ssq2[C2 * SLOTS];
__device__ double g_sum3[C3 * SLOTS], g_ssq3[C3 * SLOTS];
__device__ float  g_f2[C2 * H2 * H2];
__device__ float  g_f3[C3 * H3 * H3];
__device__ float  g_A[NPATCH * 4];
__device__ float  g_shift[2 * NPATCH];
__device__ float  g_trans[NPATCH * 6];

// ---------------- zero stats ----------------
__global__ void k_zero_stats() {
    int t = threadIdx.x;
    for (int i = t; i < C1 * SLOTS; i += 1024) { g_sum1[i] = 0; g_ssq1[i] = 0; }
    for (int i = t; i < C2 * SLOTS; i += 1024) { g_sum2[i] = 0; g_ssq2[i] = 0; }
    for (int i = t; i < C3 * SLOTS; i += 1024) { g_sum3[i] = 0; g_ssq3[i] = 0; }
}

// ---------------- K1: conv1 stats only, 2x2 px/thread ----------------
// grid (24,24), block 256; out tile 32x32
__global__ __launch_bounds__(256) void k_conv1s(const float* __restrict__ img,
                                                const float* __restrict__ w1) {
    __shared__ float sw[C1 * 9];
    __shared__ float sred[8 * C1], qred[8 * C1];
    int tid = threadIdx.x, tx = tid & 15, ty = tid >> 4;
    if (tid < C1 * 9) sw[tid] = w1[tid];
    __syncthreads();

    float s[C1], q[C1];
#pragma unroll
    for (int c = 0; c < C1; c++) { s[c] = 0.f; q[c] = 0.f; }

#pragma unroll
    for (int py = 0; py < 2; py++)
#pragma unroll
        for (int px = 0; px < 2; px++) {
            int x = blockIdx.x * 32 + tx + px * 16;
            int y = blockIdx.y * 32 + ty + py * 16;
            float v[9];
#pragma unroll
            for (int dy = 0; dy < 3; dy++)
#pragma unroll
                for (int dx = 0; dx < 3; dx++) {
                    int iy = y + dy - 1, ix = x + dx - 1;
                    v[dy * 3 + dx] = ((unsigned)iy < HW && (unsigned)ix < HW)
                                         ? img[iy * HW + ix] : 0.f;
                }
#pragma unroll
            for (int c = 0; c < C1; c++) {
                float a = 0.f;
#pragma unroll
                for (int k = 0; k < 9; k++) a += v[k] * sw[c * 9 + k];
                s[c] += a; q[c] += a * a;
            }
        }

    int lane = tid & 31, warp = tid >> 5;
    for (int c = 0; c < C1; c++) {
        float ss = s[c], qq = q[c];
        for (int d = 16; d; d >>= 1) {
            ss += __shfl_xor_sync(~0u, ss, d);
            qq += __shfl_xor_sync(~0u, qq, d);
        }
        if (lane == 0) { sred[warp * C1 + c] = ss; qred[warp * C1 + c] = qq; }
    }
    __syncthreads();
    if (tid < C1) {
        float ss = 0, qq = 0;
        for (int w8 = 0; w8 < 8; w8++) { ss += sred[w8 * C1 + tid]; qq += qred[w8 * C1 + tid]; }
        int slot = (blockIdx.y * gridDim.x + blockIdx.x) & (SLOTS - 1);
        atomicAdd(&g_sum1[tid * SLOTS + slot], (double)ss);
        atomicAdd(&g_ssq1[tid * SLOTS + slot], (double)qq);
    }
}

// ---------------- K2: fused conv1+bn1+conv2+stats2, double-buffered ----------------
// grid (12,24), block 256; out tile 32x x 16y, 2 x-px/thread, 32 outs
__global__ __launch_bounds__(256, 2) void k_conv2f(const float* __restrict__ img,
                                                   const float* __restrict__ w1,
                                                   const float* __restrict__ w2) {
    __shared__ float simg[35 * 67];
    __shared__ float sf1[2][33 * 65];
    __shared__ float sw2[2][C2 * 9];
    __shared__ float sw1[C1 * 9];
    __shared__ float sm1[C1], sr1[C1];
    __shared__ float sred[8 * C2], qred[8 * C2];

    int tid = threadIdx.x, tx = tid & 15, ty = tid >> 4;
    int ibx = 64 * blockIdx.x - 1;
    int iby = 32 * blockIdx.y - 1;

    for (int i = tid; i < 35 * 67; i += 256) {
        int r = i / 67, c = i - r * 67;
        int yy = iby - 1 + r, xx = ibx - 1 + c;
        simg[i] = ((unsigned)yy < HW && (unsigned)xx < HW) ? img[yy * HW + xx] : 0.f;
    }
    if (tid < C1 * 9) sw1[tid] = w1[tid];
    if (tid < C1) {
        double s = 0, q = 0;
        for (int j = 0; j < SLOTS; j++) { s += g_sum1[tid * SLOTS + j]; q += g_ssq1[tid * SLOTS + j]; }
        double m = s / (double)(HW * HW);
        double v = q / (double)(HW * HW) - m * m;
        sm1[tid] = (float)m;
        sr1[tid] = (float)rsqrt(v + 1e-5);
    }
    __syncthreads();   // simg, sw1, stats ready

    auto stage = [&](int b, int c1) {
        float m = sm1[c1], rs = sr1[c1];
        const float* wp = &sw1[c1 * 9];
        for (int i = tid; i < 33 * 65; i += 256) {
            int rr = i / 65, cc = i - rr * 65;
            int fy = iby + rr, fx = ibx + cc;
            float t = 0.f;
            if ((unsigned)fy < HW && (unsigned)fx < HW) {
                float a = 0.f;
#pragma unroll
                for (int dy = 0; dy < 3; dy++)
#pragma unroll
                    for (int dx = 0; dx < 3; dx++)
                        a += simg[(rr + dy) * 67 + cc + dx] * wp[dy * 3 + dx];
                t = fmaxf((a - m) * rs, 0.f);
            }
            sf1[b][i] = t;
        }
        for (int i = tid; i < C2 * 9; i += 256)
            sw2[b][i] = w2[(i / 9) * (C1 * 9) + c1 * 9 + (i % 9)];
    };

    float acc0[C2], acc1[C2];
#pragma unroll
    for (int o = 0; o < C2; o++) { acc0[o] = 0.f; acc1[o] = 0.f; }

    stage(0, 0);
    for (int c1 = 0; c1 < C1; c1++) {
        __syncthreads();                       // buf[c1&1] ready
        if (c1 + 1 < C1) stage((c1 + 1) & 1, c1 + 1);

        const float* f = sf1[c1 & 1];
        const float* w = sw2[c1 & 1];
        float v0[9], v1[9];
#pragma unroll
        for (int kh = 0; kh < 3; kh++)
#pragma unroll
            for (int kw = 0; kw < 3; kw++) {
                v0[kh * 3 + kw] = f[(2 * ty + kh) * 65 + 2 * tx + kw];
                v1[kh * 3 + kw] = f[(2 * ty + kh) * 65 + 2 * tx + 32 + kw];
            }
#pragma unroll
        for (int o = 0; o < C2; o++) {
            float a0 = acc0[o], a1 = acc1[o];
#pragma unroll
            for (int k = 0; k < 9; k++) {
                float wf = w[o * 9 + k];
                a0 += v0[k] * wf;
                a1 += v1[k] * wf;
            }
            acc0[o] = a0; acc1[o] = a1;
        }
    }

    int oy = blockIdx.y * 16 + ty, ox = blockIdx.x * 32 + tx;
#pragma unroll
    for (int o = 0; o < C2; o++) {
        g_f2[(size_t)o * H2 * H2 + (size_t)oy * H2 + ox]      = acc0[o];
        g_f2[(size_t)o * H2 * H2 + (size_t)oy * H2 + ox + 16] = acc1[o];
    }
    int lane = tid & 31, warp = tid >> 5;
    for (int o = 0; o < C2; o++) {
        float s = acc0[o] + acc1[o];
        float q = acc0[o] * acc0[o] + acc1[o] * acc1[o];
        for (int d = 16; d; d >>= 1) {
            s += __shfl_xor_sync(~0u, s, d);
            q += __shfl_xor_sync(~0u, q, d);
        }
        if (lane == 0) { sred[warp * C2 + o] = s; qred[warp * C2 + o] = q; }
    }
    __syncthreads();
    if (tid < C2) {
        float s = 0, q = 0;
        for (int w8 = 0; w8 < 8; w8++) { s += sred[w8 * C2 + tid]; q += qred[w8 * C2 + tid]; }
        int slot = (blockIdx.y * gridDim.x + blockIdx.x) & (SLOTS - 1);
        atomicAdd(&g_sum2[tid * SLOTS + slot], (double)s);
        atomicAdd(&g_ssq2[tid * SLOTS + slot], (double)q);
    }
}

// ---------------- K3: bn2+conv3+stats3, double-buffered, 2x2 px ----------------
// grid (6,6,8), block 256; out tile 32x32, 8 outs per z-group
__global__ __launch_bounds__(256, 2) void k_conv3f(const float* __restrict__ w3) {
    __shared__ float sf[2][65 * 65];
    __shared__ float sw[2][8 * 9];
    __shared__ float sm2[C2], sr2[C2];
    __shared__ float sred[8 * 8], qred[8 * 8];

    int tid = threadIdx.x, tx = tid & 15, ty = tid >> 4;
    int ibx = 64 * blockIdx.x - 1;
    int iby = 64 * blockIdx.y - 1;
    int obase = blockIdx.z * 8;

    if (tid < C2) {
        double s = 0, q = 0;
        for (int j = 0; j < SLOTS; j++) { s += g_sum2[tid * SLOTS + j]; q += g_ssq2[tid * SLOTS + j]; }
        double m = s / (double)(H2 * H2);
        double v = q / (double)(H2 * H2) - m * m;
        sm2[tid] = (float)m;
        sr2[tid] = (float)rsqrt(v + 1e-5);
    }
    __syncthreads();   // stats ready

    auto stage = [&](int b, int c) {
        float m = sm2[c], rs = sr2[c];
        const float* ic = g_f2 + (size_t)c * H2 * H2;
        for (int i = tid; i < 65 * 65; i += 256) {
            int rr = i / 65, cc = i - rr * 65;
            int fy = iby + rr, fx = ibx + cc;
            float t = 0.f;
            if ((unsigned)fy < H2 && (unsigned)fx < H2)
                t = fmaxf((ic[(size_t)fy * H2 + fx] - m) * rs, 0.f);
            sf[b][i] = t;
        }
        if (tid < 8 * 9)
            sw[b][tid] = w3[(obase + tid / 9) * (C2 * 9) + c * 9 + (tid % 9)];
    };

    float acc[8][4];
#pragma unroll
    for (int o = 0; o < 8; o++)
#pragma unroll
        for (int p = 0; p < 4; p++) acc[o][p] = 0.f;

    stage(0, 0);
    for (int c = 0; c < C2; c++) {
        __syncthreads();
        if (c + 1 < C2) stage((c + 1) & 1, c + 1);

        const float* f = sf[c & 1];
        const float* w = sw[c & 1];
        float v[2][2][9];
#pragma unroll
        for (int py = 0; py < 2; py++) {
            int ry = 2 * ty + 32 * py;
#pragma unroll
            for (int px = 0; px < 2; px++) {
                int cx = 2 * tx + 32 * px;
#pragma unroll
                for (int kh = 0; kh < 3; kh++)
#pragma unroll
                    for (int kw = 0; kw < 3; kw++)
                        v[py][px][kh * 3 + kw] = f[(ry + kh) * 65 + cx + kw];
            }
        }
#pragma unroll
        for (int o = 0; o < 8; o++) {
#pragma unroll
            for (int k = 0; k < 9; k++) {
                float wf = w[o * 9 + k];
                acc[o][0] += v[0][0][k] * wf;
                acc[o][1] += v[0][1][k] * wf;
                acc[o][2] += v[1][0][k] * wf;
                acc[o][3] += v[1][1][k] * wf;
            }
        }
    }

#pragma unroll
    for (int o = 0; o < 8; o++)
#pragma unroll
        for (int py = 0; py < 2; py++)
#pragma unroll
            for (int px = 0; px < 2; px++) {
                int oy = blockIdx.y * 32 + ty + 16 * py;
                int ox = blockIdx.x * 32 + tx + 16 * px;
                g_f3[(size_t)(obase + o) * H3 * H3 + (size_t)oy * H3 + ox] =
                    acc[o][py * 2 + px];
            }

    int lane = tid & 31, warp = tid >> 5;
    for (int o = 0; o < 8; o++) {
        float s = acc[o][0] + acc[o][1] + acc[o][2] + acc[o][3];
        float q = acc[o][0] * acc[o][0] + acc[o][1] * acc[o][1] +
                  acc[o][2] * acc[o][2] + acc[o][3] * acc[o][3];
        for (int d = 16; d; d >>= 1) {
            s += __shfl_xor_sync(~0u, s, d);
            q += __shfl_xor_sync(~0u, q, d);
        }
        if (lane == 0) { sred[warp * 8 + o] = s; qred[warp * 8 + o] = q; }
    }
    __syncthreads();
    if (tid < 8) {
        float s = 0, q = 0;
        for (int w8 = 0; w8 < 8; w8++) { s += sred[w8 * 8 + tid]; q += qred[w8 * 8 + tid]; }
        int slot = (blockIdx.y * gridDim.x + blockIdx.x) & (SLOTS - 1);
        atomicAdd(&g_sum3[(obase + tid) * SLOTS + slot], (double)s);
        atomicAdd(&g_ssq3[(obase + tid) * SLOTS + slot], (double)q);
    }
}

// ---------------- heads ----------------
__global__ __launch_bounds__(256) void k_heads(
    const float* __restrict__ pw, const float* __restrict__ pb,
    const float* __restrict__ tw, const float* __restrict__ tb,
    const float* __restrict__ shw, const float* __restrict__ shb,
    const float* __restrict__ scw, const float* __restrict__ scb,
    const float* __restrict__ tiw, const float* __restrict__ tib) {
    __shared__ float sm3[C3], sr3[C3];
    int tid = threadIdx.x;
    if (tid < C3) {
        double s = 0, q = 0;
        for (int j = 0; j < SLOTS; j++) { s += g_sum3[tid * SLOTS + j]; q += g_ssq3[tid * SLOTS + j]; }
        double m = s / (double)(H3 * H3);
        double v = q / (double)(H3 * H3) - m * m;
        sm3[tid] = (float)m;
        sr3[tid] = (float)rsqrt(v + 1e-5);
    }
    __syncthreads();

    int p = blockIdx.x * blockDim.x + tid;
    if (p >= NPATCH) return;
    int gx = p % NG, gy = p / NG;

    float ap = 0, at = 0, as0 = 0, as1 = 0, asc = 0, ati = 0;
    for (int c = 0; c < C3; c++) {
        float m = sm3[c], r = sr3[c];
        const float* fc = g_f3 + (size_t)c * H3 * H3 + (size_t)(2 * gy) * H3 + 2 * gx;
#pragma unroll
        for (int kh = 0; kh < 2; kh++)
#pragma unroll
            for (int kw = 0; kw < 2; kw++) {
                float v = fmaxf((fc[kh * H3 + kw] - m) * r, 0.f);
                int wi = c * 4 + kh * 2 + kw;
                ap  += v * pw[wi];
                at  += v * tw[wi];
                as0 += v * shw[wi];
                as1 += v * shw[256 + wi];
                asc += v * scw[wi];
                ati += v * tiw[wi];
            }
    }
    float psi = 3.14159f * tanhf(ap + pb[0]);
    float th  = 3.14159f * tanhf(at + tb[0]);
    float s0  = 0.2f * tanhf(as0 + shb[0]);
    float s1  = 0.2f * tanhf(as1 + shb[1]);
    float sc  = fminf(fmaxf(1.f + 0.25f * tanhf(asc + scb[0]), 0.8f), 1.25f);
    float ti  = fminf(fmaxf(1.f + 0.8f  * tanhf(ati + tib[0]), 1.0f), 1.8f);

    float cp = cosf(psi), sp = sinf(psi);
    float ct = cosf(th),  st = sinf(th);
    float M00 = ti * ct, M01 = -ti * st;
    float M10 = st / ti, M11 = ct / ti;
    g_A[p * 4 + 0] = sc * (cp * M00 - sp * M10);
    g_A[p * 4 + 1] = sc * (cp * M01 - sp * M11);
    g_A[p * 4 + 2] = sc * (sp * M00 + cp * M10);
    g_A[p * 4 + 3] = sc * (sp * M01 + cp * M11);
    g_shift[p]          = s0;
    g_shift[NPATCH + p] = s1;
}

// ---------------- assemble ----------------
__global__ void k_assemble(float* __restrict__ out) {
    int n = blockIdx.x * blockDim.x + threadIdx.x;
    if (n >= NPATCH) return;
    float t0 = g_A[n * 4 + 0], t1 = g_A[n * 4 + 1];
    float t3 = g_A[n * 4 + 2], t4 = g_A[n * 4 + 3];
    float t2 = g_shift[2 * n];
    float t5 = g_shift[2 * n + 1];
    g_trans[n * 6 + 0] = t0; g_trans[n * 6 + 1] = t1; g_trans[n * 6 + 2] = t2;
    g_trans[n * 6 + 3] = t3; g_trans[n * 6 + 4] = t4; g_trans[n * 6 + 5] = t5;

    float cx = 4.f + 8.f * (float)(n % NG);
    float cy = 4.f + 8.f * (float)(n / NG);
    float* a = out + (size_t)NPATCH * 1024 + (size_t)n * 6;
    a[0] = 32.f * t0; a[1] = 32.f * t1; a[2] = cx + 32.f * t2;
    a[3] = 32.f * t3; a[4] = 32.f * t4; a[5] = cy + 32.f * t5;
}

// ---------------- bilinear sampler ----------------
__global__ __launch_bounds__(1024) void k_sample(const float* __restrict__ img,
                                                 float* __restrict__ out) {
    int n = blockIdx.x;
    __shared__ float t[6];
    if (threadIdx.x < 6) t[threadIdx.x] = g_trans[n * 6 + threadIdx.x];
    __syncthreads();

    int w = threadIdx.x & 31, h = threadIdx.x >> 5;
    float X = ((float)w + 0.5f) * (2.f / 32.f) - 1.f;
    float Y = ((float)h + 0.5f) * (2.f / 32.f) - 1.f;
    float gx = (X * t[0] + Y * t[1] + t[2]) / 4.5f;
    float gy = (X * t[3] + Y * t[4] + t[5]) / 4.5f;
    float ix = ((gx + 1.f) * 144.f - 1.f) * 0.5f;
    float iy = ((gy + 1.f) * 144.f - 1.f) * 0.5f;
    float x0f = floorf(ix), y0f = floorf(iy);
    float wx = ix - x0f, wy = iy - y0f;
    int x0 = (int)x0f, y0 = (int)y0f;
    int bx = (n % NG) * 8 - PADO;
    int by = (n / NG) * 8 - PADO;

    auto g = [&](int yy, int xx) -> float {
        if ((unsigned)yy >= GPS || (unsigned)xx >= GPS) return 0.f;
        int ir = by + yy, ic = bx + xx;
        if ((unsigned)ir >= HW || (unsigned)ic >= HW) return 0.f;
        return img[(size_t)ir * HW + ic];
    };
    float v = (1.f - wy) * ((1.f - wx) * g(y0, x0)     + wx * g(y0, x0 + 1)) +
              wy        * ((1.f - wx) * g(y0 + 1, x0) + wx * g(y0 + 1, x0 + 1));
    out[(size_t)n * 1024 + threadIdx.x] = v;
}

// ---------------- launch ----------------
extern "C" void kernel_launch(void* const* d_in, const int* in_sizes, int n_in,
                              void* d_out, int out_size) {
    const float* img = (const float*)d_in[0];
    const float* w1  = (const float*)d_in[1];
    const float* w2  = (const float*)d_in[2];
    const float* w3  = (const float*)d_in[3];
    const float* pw  = (const float*)d_in[4];
    const float* pb  = (const float*)d_in[5];
    const float* tw  = (const float*)d_in[6];
    const float* tb  = (const float*)d_in[7];
    const float* shw = (const float*)d_in[8];
    const float* shb = (const float*)d_in[9];
    const float* scw = (const float*)d_in[10];
    const float* scb = (const float*)d_in[11];
    const float* tiw = (const float*)d_in[12];
    const float* tib = (const float*)d_in[13];
    float* out = (float*)d_out;

    k_zero_stats<<<1, 1024>>>();
    k_conv1s<<<dim3(24, 24), 256>>>(img, w1);
    k_conv2f<<<dim3(12, 24), 256>>>(img, w1, w2);
    k_conv3f<<<dim3(6, 6, 8), 256>>>(w3);
    k_heads<<<36, 256>>>(pw, pb, tw, tb, shw, shb, scw, scb, tiw, tib);
    k_assemble<<<36, 256>>>(out);
    k_sample<<<NPATCH, 1024>>>(img, out);
}

// round 5
// speedup vs baseline: 1.3584x; 1.1463x over previous
#include <cuda_runtime.h>
#include <math.h>

// ---------------- constants ----------------
#define HW      768
#define C1      16
#define C2      32
#define C3      64
#define H2      384
#define H3      192
#define NG      96
#define NPATCH  9216
#define GPS     144
#define PADO    68
#define SLOTS   32
// padded normalized f2: [C2][386][392], halo of zeros, x/y shifted by +1
#define NPH     386
#define NPW     392

// ---------------- device scratch ----------------
__device__ double g_sum1[C1 * SLOTS], g_ssq1[C1 * SLOTS];
__device__ double g_sum2[C2 * SLOTS], g_ssq2[C2 * SLOTS];
__device__ double g_sum3[C3 * SLOTS], g_ssq3[C3 * SLOTS];
__device__ float  g_f2[C2 * H2 * H2];
__device__ float  g_nf2[C2 * NPH * NPW];
__device__ float  g_f3[C3 * H3 * H3];
__device__ float  g_hpart[8][6 * NPATCH];
__device__ float  g_A[NPATCH * 4];
__device__ float  g_shift[2 * NPATCH];
__device__ float  g_trans[NPATCH * 6];

// ---------------- zero stats ----------------
__global__ void k_zero_stats() {
    int t = threadIdx.x;
    for (int i = t; i < C1 * SLOTS; i += 1024) { g_sum1[i] = 0; g_ssq1[i] = 0; }
    for (int i = t; i < C2 * SLOTS; i += 1024) { g_sum2[i] = 0; g_ssq2[i] = 0; }
    for (int i = t; i < C3 * SLOTS; i += 1024) { g_sum3[i] = 0; g_ssq3[i] = 0; }
}

// ---------------- K1: conv1 stats only, 2x2 px/thread ----------------
__global__ __launch_bounds__(256) void k_conv1s(const float* __restrict__ img,
                                                const float* __restrict__ w1) {
    __shared__ float sw[C1 * 9];
    __shared__ float sred[8 * C1], qred[8 * C1];
    int tid = threadIdx.x, tx = tid & 15, ty = tid >> 4;
    if (tid < C1 * 9) sw[tid] = w1[tid];
    __syncthreads();

    float s[C1], q[C1];
#pragma unroll
    for (int c = 0; c < C1; c++) { s[c] = 0.f; q[c] = 0.f; }

#pragma unroll
    for (int py = 0; py < 2; py++)
#pragma unroll
        for (int px = 0; px < 2; px++) {
            int x = blockIdx.x * 32 + tx + px * 16;
            int y = blockIdx.y * 32 + ty + py * 16;
            float v[9];
#pragma unroll
            for (int dy = 0; dy < 3; dy++)
#pragma unroll
                for (int dx = 0; dx < 3; dx++) {
                    int iy = y + dy - 1, ix = x + dx - 1;
                    v[dy * 3 + dx] = ((unsigned)iy < HW && (unsigned)ix < HW)
                                         ? img[iy * HW + ix] : 0.f;
                }
#pragma unroll
            for (int c = 0; c < C1; c++) {
                float a = 0.f;
#pragma unroll
                for (int k = 0; k < 9; k++) a += v[k] * sw[c * 9 + k];
                s[c] += a; q[c] += a * a;
            }
        }

    int lane = tid & 31, warp = tid >> 5;
    for (int c = 0; c < C1; c++) {
        float ss = s[c], qq = q[c];
        for (int d = 16; d; d >>= 1) {
            ss += __shfl_xor_sync(~0u, ss, d);
            qq += __shfl_xor_sync(~0u, qq, d);
        }
        if (lane == 0) { sred[warp * C1 + c] = ss; qred[warp * C1 + c] = qq; }
    }
    __syncthreads();
    if (tid < C1) {
        float ss = 0, qq = 0;
        for (int w8 = 0; w8 < 8; w8++) { ss += sred[w8 * C1 + tid]; qq += qred[w8 * C1 + tid]; }
        int slot = (blockIdx.y * gridDim.x + blockIdx.x) & (SLOTS - 1);
        atomicAdd(&g_sum1[tid * SLOTS + slot], (double)ss);
        atomicAdd(&g_ssq1[tid * SLOTS + slot], (double)qq);
    }
}

// ---------------- K2: fused conv1+bn1+conv2+stats2, double-buffered ----------------
__global__ __launch_bounds__(256, 2) void k_conv2f(const float* __restrict__ img,
                                                   const float* __restrict__ w1,
                                                   const float* __restrict__ w2) {
    __shared__ float simg[35 * 67];
    __shared__ float sf1[2][33 * 65];
    __shared__ float sw2[2][C2 * 9];
    __shared__ float sw1[C1 * 9];
    __shared__ float sm1[C1], sr1[C1];
    __shared__ float sred[8 * C2], qred[8 * C2];

    int tid = threadIdx.x, tx = tid & 15, ty = tid >> 4;
    int ibx = 64 * blockIdx.x - 1;
    int iby = 32 * blockIdx.y - 1;

    for (int i = tid; i < 35 * 67; i += 256) {
        int r = i / 67, c = i - r * 67;
        int yy = iby - 1 + r, xx = ibx - 1 + c;
        simg[i] = ((unsigned)yy < HW && (unsigned)xx < HW) ? img[yy * HW + xx] : 0.f;
    }
    if (tid < C1 * 9) sw1[tid] = w1[tid];
    if (tid < C1) {
        double s = 0, q = 0;
        for (int j = 0; j < SLOTS; j++) { s += g_sum1[tid * SLOTS + j]; q += g_ssq1[tid * SLOTS + j]; }
        double m = s / (double)(HW * HW);
        double v = q / (double)(HW * HW) - m * m;
        sm1[tid] = (float)m;
        sr1[tid] = (float)rsqrt(v + 1e-5);
    }
    __syncthreads();

    auto stage = [&](int b, int c1) {
        float m = sm1[c1], rs = sr1[c1];
        const float* wp = &sw1[c1 * 9];
        for (int i = tid; i < 33 * 65; i += 256) {
            int rr = i / 65, cc = i - rr * 65;
            int fy = iby + rr, fx = ibx + cc;
            float t = 0.f;
            if ((unsigned)fy < HW && (unsigned)fx < HW) {
                float a = 0.f;
#pragma unroll
                for (int dy = 0; dy < 3; dy++)
#pragma unroll
                    for (int dx = 0; dx < 3; dx++)
                        a += simg[(rr + dy) * 67 + cc + dx] * wp[dy * 3 + dx];
                t = fmaxf((a - m) * rs, 0.f);
            }
            sf1[b][i] = t;
        }
        for (int i = tid; i < C2 * 9; i += 256)
            sw2[b][i] = w2[(i / 9) * (C1 * 9) + c1 * 9 + (i % 9)];
    };

    float acc0[C2], acc1[C2];
#pragma unroll
    for (int o = 0; o < C2; o++) { acc0[o] = 0.f; acc1[o] = 0.f; }

    stage(0, 0);
    for (int c1 = 0; c1 < C1; c1++) {
        __syncthreads();
        if (c1 + 1 < C1) stage((c1 + 1) & 1, c1 + 1);

        const float* f = sf1[c1 & 1];
        const float* w = sw2[c1 & 1];
        float v0[9], v1[9];
#pragma unroll
        for (int kh = 0; kh < 3; kh++)
#pragma unroll
            for (int kw = 0; kw < 3; kw++) {
                v0[kh * 3 + kw] = f[(2 * ty + kh) * 65 + 2 * tx + kw];
                v1[kh * 3 + kw] = f[(2 * ty + kh) * 65 + 2 * tx + 32 + kw];
            }
#pragma unroll
        for (int o = 0; o < C2; o++) {
            float a0 = acc0[o], a1 = acc1[o];
#pragma unroll
            for (int k = 0; k < 9; k++) {
                float wf = w[o * 9 + k];
                a0 += v0[k] * wf;
                a1 += v1[k] * wf;
            }
            acc0[o] = a0; acc1[o] = a1;
        }
    }

    int oy = blockIdx.y * 16 + ty, ox = blockIdx.x * 32 + tx;
#pragma unroll
    for (int o = 0; o < C2; o++) {
        g_f2[(size_t)o * H2 * H2 + (size_t)oy * H2 + ox]      = acc0[o];
        g_f2[(size_t)o * H2 * H2 + (size_t)oy * H2 + ox + 16] = acc1[o];
    }
    int lane = tid & 31, warp = tid >> 5;
    for (int o = 0; o < C2; o++) {
        float s = acc0[o] + acc1[o];
        float q = acc0[o] * acc0[o] + acc1[o] * acc1[o];
        for (int d = 16; d; d >>= 1) {
            s += __shfl_xor_sync(~0u, s, d);
            q += __shfl_xor_sync(~0u, q, d);
        }
        if (lane == 0) { sred[warp * C2 + o] = s; qred[warp * C2 + o] = q; }
    }
    __syncthreads();
    if (tid < C2) {
        float s = 0, q = 0;
        for (int w8 = 0; w8 < 8; w8++) { s += sred[w8 * C2 + tid]; q += qred[w8 * C2 + tid]; }
        int slot = (blockIdx.y * gridDim.x + blockIdx.x) & (SLOTS - 1);
        atomicAdd(&g_sum2[tid * SLOTS + slot], (double)s);
        atomicAdd(&g_ssq2[tid * SLOTS + slot], (double)q);
    }
}

// ---------------- bn2: normalize f2 into zero-padded g_nf2 ----------------
// grid (74, 32), block 256
__global__ __launch_bounds__(256) void k_bn2() {
    int c = blockIdx.y;
    __shared__ float s_m, s_r;
    if (threadIdx.x == 0) {
        double s = 0, q = 0;
        for (int j = 0; j < SLOTS; j++) { s += g_sum2[c * SLOTS + j]; q += g_ssq2[c * SLOTS + j]; }
        double m = s / (double)(H2 * H2);
        double v = q / (double)(H2 * H2) - m * m;
        s_m = (float)m;
        s_r = (float)rsqrt(v + 1e-5);
    }
    __syncthreads();
    float m = s_m, r = s_r;
    const float* src = g_f2 + (size_t)c * H2 * H2;
    float* dst = g_nf2 + (size_t)c * NPH * NPW;
    for (int i = blockIdx.x * 256 + threadIdx.x; i < NPH * NPW; i += 74 * 256) {
        int y = i / NPW, x = i - y * NPW;
        float t = 0.f;
        int sy = y - 1, sx = x - 1;
        if ((unsigned)sy < H2 && (unsigned)sx < H2)
            t = fmaxf((src[sy * H2 + sx] - m) * r, 0.f);
        dst[i] = t;
    }
}

// ---------------- K3: conv3 from g_nf2 (vectorized staging), stats3 ----------------
// grid (6,12,4), block 256; out tile 32x x 16y, 2 x-px/thread, 16 outs per z
__global__ __launch_bounds__(256, 3) void k_conv3f(const float* __restrict__ w3) {
    __shared__ float sf[2][33 * 68];
    __shared__ float sw[2][16 * 9];
    __shared__ float sred[8 * 16], qred[8 * 16];

    int tid = threadIdx.x, tx = tid & 15, ty = tid >> 4;
    int colbase = 64 * blockIdx.x;        // padded col of input origin (orig x=-1)
    int rowbase = 32 * blockIdx.y;        // padded row of input origin (orig y=-1)
    int obase = blockIdx.z * 16;

    auto stage = [&](int b, int c) {
        const float* src = g_nf2 + (size_t)c * NPH * NPW;
        // 33 rows x 17 float4 (68 cols; only 65 used by compute)
        for (int i = tid; i < 33 * 17; i += 256) {
            int r = i / 17, q4 = i - r * 17;
            const float4* s4 =
                (const float4*)(src + (size_t)(rowbase + r) * NPW + colbase) + q4;
            ((float4*)&sf[b][r * 68])[q4] = *s4;
        }
        if (tid < 16 * 9)
            sw[b][tid] = w3[(obase + tid / 9) * (C2 * 9) + c * 9 + (tid % 9)];
    };

    float acc0[16], acc1[16];
#pragma unroll
    for (int o = 0; o < 16; o++) { acc0[o] = 0.f; acc1[o] = 0.f; }

    stage(0, 0);
    for (int c = 0; c < C2; c++) {
        __syncthreads();
        if (c + 1 < C2) stage((c + 1) & 1, c + 1);

        const float* f = sf[c & 1];
        const float* w = sw[c & 1];
        float v0[9], v1[9];
#pragma unroll
        for (int kh = 0; kh < 3; kh++)
#pragma unroll
            for (int kw = 0; kw < 3; kw++) {
                v0[kh * 3 + kw] = f[(2 * ty + kh) * 68 + 2 * tx + kw];
                v1[kh * 3 + kw] = f[(2 * ty + kh) * 68 + 2 * tx + 32 + kw];
            }
#pragma unroll
        for (int o = 0; o < 16; o++) {
            float a0 = acc0[o], a1 = acc1[o];
#pragma unroll
            for (int k = 0; k < 9; k++) {
                float wf = w[o * 9 + k];
                a0 += v0[k] * wf;
                a1 += v1[k] * wf;
            }
            acc0[o] = a0; acc1[o] = a1;
        }
    }

    int oy = blockIdx.y * 16 + ty, ox = blockIdx.x * 32 + tx;
#pragma unroll
    for (int o = 0; o < 16; o++) {
        g_f3[(size_t)(obase + o) * H3 * H3 + (size_t)oy * H3 + ox]      = acc0[o];
        g_f3[(size_t)(obase + o) * H3 * H3 + (size_t)oy * H3 + ox + 16] = acc1[o];
    }

    int lane = tid & 31, warp = tid >> 5;
    for (int o = 0; o < 16; o++) {
        float s = acc0[o] + acc1[o];
        float q = acc0[o] * acc0[o] + acc1[o] * acc1[o];
        for (int d = 16; d; d >>= 1) {
            s += __shfl_xor_sync(~0u, s, d);
            q += __shfl_xor_sync(~0u, q, d);
        }
        if (lane == 0) { sred[warp * 16 + o] = s; qred[warp * 16 + o] = q; }
    }
    __syncthreads();
    if (tid < 16) {
        float s = 0, q = 0;
        for (int w8 = 0; w8 < 8; w8++) { s += sred[w8 * 16 + tid]; q += qred[w8 * 16 + tid]; }
        int slot = ((blockIdx.z * gridDim.y + blockIdx.y) * gridDim.x + blockIdx.x) & (SLOTS - 1);
        atomicAdd(&g_sum3[(obase + tid) * SLOTS + slot], (double)s);
        atomicAdd(&g_ssq3[(obase + tid) * SLOTS + slot], (double)q);
    }
}

// ---------------- heads: partial dot-products, 8-channel groups ----------------
// grid (36, 8), block 256
__global__ __launch_bounds__(256) void k_heads_acc(
    const float* __restrict__ pw, const float* __restrict__ tw,
    const float* __restrict__ shw, const float* __restrict__ scw,
    const float* __restrict__ tiw) {
    int cg = blockIdx.y;
    __shared__ float sm3[8], sr3[8];
    int tid = threadIdx.x;
    if (tid < 8) {
        int c = cg * 8 + tid;
        double s = 0, q = 0;
        for (int j = 0; j < SLOTS; j++) { s += g_sum3[c * SLOTS + j]; q += g_ssq3[c * SLOTS + j]; }
        double m = s / (double)(H3 * H3);
        double v = q / (double)(H3 * H3) - m * m;
        sm3[tid] = (float)m;
        sr3[tid] = (float)rsqrt(v + 1e-5);
    }
    __syncthreads();

    int p = blockIdx.x * 256 + tid;
    int gx = p % NG, gy = p / NG;

    float ap = 0, at = 0, as0 = 0, as1 = 0, asc = 0, ati = 0;
#pragma unroll
    for (int cc = 0; cc < 8; cc++) {
        int c = cg * 8 + cc;
        float m = sm3[cc], r = sr3[cc];
        const float* fc = g_f3 + (size_t)c * H3 * H3 + (size_t)(2 * gy) * H3 + 2 * gx;
#pragma unroll
        for (int kh = 0; kh < 2; kh++)
#pragma unroll
            for (int kw = 0; kw < 2; kw++) {
                float v = fmaxf((fc[kh * H3 + kw] - m) * r, 0.f);
                int wi = c * 4 + kh * 2 + kw;
                ap  += v * pw[wi];
                at  += v * tw[wi];
                as0 += v * shw[wi];
                as1 += v * shw[256 + wi];
                asc += v * scw[wi];
                ati += v * tiw[wi];
            }
    }
    float* part = g_hpart[cg];
    part[0 * NPATCH + p] = ap;
    part[1 * NPATCH + p] = at;
    part[2 * NPATCH + p] = as0;
    part[3 * NPATCH + p] = as1;
    part[4 * NPATCH + p] = asc;
    part[5 * NPATCH + p] = ati;
}

// finalize heads: sum partials, bias, tanh, trig -> g_A, g_shift
__global__ __launch_bounds__(256) void k_heads_fin(
    const float* __restrict__ pb, const float* __restrict__ tb,
    const float* __restrict__ shb, const float* __restrict__ scb,
    const float* __restrict__ tib) {
    int p = blockIdx.x * 256 + threadIdx.x;
    float a[6] = {0, 0, 0, 0, 0, 0};
#pragma unroll
    for (int g = 0; g < 8; g++)
#pragma unroll
        for (int j = 0; j < 6; j++) a[j] += g_hpart[g][j * NPATCH + p];

    float psi = 3.14159f * tanhf(a[0] + pb[0]);
    float th  = 3.14159f * tanhf(a[1] + tb[0]);
    float s0  = 0.2f * tanhf(a[2] + shb[0]);
    float s1  = 0.2f * tanhf(a[3] + shb[1]);
    float sc  = fminf(fmaxf(1.f + 0.25f * tanhf(a[4] + scb[0]), 0.8f), 1.25f);
    float ti  = fminf(fmaxf(1.f + 0.8f  * tanhf(a[5] + tib[0]), 1.0f), 1.8f);

    float cp = cosf(psi), sp = sinf(psi);
    float ct = cosf(th),  st = sinf(th);
    float M00 = ti * ct, M01 = -ti * st;
    float M10 = st / ti, M11 = ct / ti;
    g_A[p * 4 + 0] = sc * (cp * M00 - sp * M10);
    g_A[p * 4 + 1] = sc * (cp * M01 - sp * M11);
    g_A[p * 4 + 2] = sc * (sp * M00 + cp * M10);
    g_A[p * 4 + 3] = sc * (sp * M01 + cp * M11);
    g_shift[p]          = s0;
    g_shift[NPATCH + p] = s1;
}

// ---------------- assemble (shift cross-channel reindex) + aff ----------------
__global__ void k_assemble(float* __restrict__ out) {
    int n = blockIdx.x * blockDim.x + threadIdx.x;
    if (n >= NPATCH) return;
    float t0 = g_A[n * 4 + 0], t1 = g_A[n * 4 + 1];
    float t3 = g_A[n * 4 + 2], t4 = g_A[n * 4 + 3];
    float t2 = g_shift[2 * n];
    float t5 = g_shift[2 * n + 1];
    g_trans[n * 6 + 0] = t0; g_trans[n * 6 + 1] = t1; g_trans[n * 6 + 2] = t2;
    g_trans[n * 6 + 3] = t3; g_trans[n * 6 + 4] = t4; g_trans[n * 6 + 5] = t5;

    float cx = 4.f + 8.f * (float)(n % NG);
    float cy = 4.f + 8.f * (float)(n / NG);
    float* a = out + (size_t)NPATCH * 1024 + (size_t)n * 6;
    a[0] = 32.f * t0; a[1] = 32.f * t1; a[2] = cx + 32.f * t2;
    a[3] = 32.f * t3; a[4] = 32.f * t4; a[5] = cy + 32.f * t5;
}

// ---------------- bilinear sampler ----------------
__global__ __launch_bounds__(1024) void k_sample(const float* __restrict__ img,
                                                 float* __restrict__ out) {
    int n = blockIdx.x;
    __shared__ float t[6];
    if (threadIdx.x < 6) t[threadIdx.x] = g_trans[n * 6 + threadIdx.x];
    __syncthreads();

    int w = threadIdx.x & 31, h = threadIdx.x >> 5;
    float X = ((float)w + 0.5f) * (2.f / 32.f) - 1.f;
    float Y = ((float)h + 0.5f) * (2.f / 32.f) - 1.f;
    float gx = (X * t[0] + Y * t[1] + t[2]) / 4.5f;
    float gy = (X * t[3] + Y * t[4] + t[5]) / 4.5f;
    float ix = ((gx + 1.f) * 144.f - 1.f) * 0.5f;
    float iy = ((gy + 1.f) * 144.f - 1.f) * 0.5f;
    float x0f = floorf(ix), y0f = floorf(iy);
    float wx = ix - x0f, wy = iy - y0f;
    int x0 = (int)x0f, y0 = (int)y0f;
    int bx = (n % NG) * 8 - PADO;
    int by = (n / NG) * 8 - PADO;

    auto g = [&](int yy, int xx) -> float {
        if ((unsigned)yy >= GPS || (unsigned)xx >= GPS) return 0.f;
        int ir = by + yy, ic = bx + xx;
        if ((unsigned)ir >= HW || (unsigned)ic >= HW) return 0.f;
        return img[(size_t)ir * HW + ic];
    };
    float v = (1.f - wy) * ((1.f - wx) * g(y0, x0)     + wx * g(y0, x0 + 1)) +
              wy        * ((1.f - wx) * g(y0 + 1, x0) + wx * g(y0 + 1, x0 + 1));
    out[(size_t)n * 1024 + threadIdx.x] = v;
}

// ---------------- launch ----------------
extern "C" void kernel_launch(void* const* d_in, const int* in_sizes, int n_in,
                              void* d_out, int out_size) {
    const float* img = (const float*)d_in[0];
    const float* w1  = (const float*)d_in[1];
    const float* w2  = (const float*)d_in[2];
    const float* w3  = (const float*)d_in[3];
    const float* pw  = (const float*)d_in[4];
    const float* pb  = (const float*)d_in[5];
    const float* tw  = (const float*)d_in[6];
    const float* tb  = (const float*)d_in[7];
    const float* shw = (const float*)d_in[8];
    const float* shb = (const float*)d_in[9];
    const float* scw = (const float*)d_in[10];
    const float* scb = (const float*)d_in[11];
    const float* tiw = (const float*)d_in[12];
    const float* tib = (const float*)d_in[13];
    float* out = (float*)d_out;

    k_zero_stats<<<1, 1024>>>();
    k_conv1s<<<dim3(24, 24), 256>>>(img, w1);
    k_conv2f<<<dim3(12, 24), 256>>>(img, w1, w2);
    k_bn2<<<dim3(74, 32), 256>>>();
    k_conv3f<<<dim3(6, 12, 4), 256>>>(w3);
    k_heads_acc<<<dim3(36, 8), 256>>>(pw, tw, shw, scw, tiw);
    k_heads_fin<<<36, 256>>>(pb, tb, shb, scb, tib);
    k_assemble<<<36, 256>>>(out);
    k_sample<<<NPATCH, 1024>>>(img, out);
}

// round 7
// speedup vs baseline: 1.4772x; 1.0874x over previous
#include <cuda_runtime.h>
#include <math.h>

// ---------------- constants ----------------
#define HW      768
#define C1      16
#define C2      32
#define C3      64
#define H2      384
#define H3      192
#define NG      96
#define NPATCH  9216
#define GPS     144
#define PADO    68
#define SLOTS   32
// padded (raw then normalized in-place) f2: [C2][386][392], 1-px halo (zeros)
#define NPH     386
#define NPW     392

// ---------------- device scratch ----------------
__device__ double g_sum1[C1 * SLOTS], g_ssq1[C1 * SLOTS];
__device__ double g_sum2[C2 * SLOTS], g_ssq2[C2 * SLOTS];
__device__ double g_sum3[C3 * SLOTS], g_ssq3[C3 * SLOTS];
__device__ float  g_nf2[C2 * NPH * NPW];
__device__ float  g_f3[C3 * H3 * H3];
__device__ float  g_hpart[8][6 * NPATCH];
__device__ float  g_A[NPATCH * 4];
__device__ float  g_shift[2 * NPATCH];
__device__ float  g_trans[NPATCH * 6];

// ---------------- zero stats ----------------
__global__ void k_zero_stats() {
    int t = threadIdx.x;
    for (int i = t; i < C1 * SLOTS; i += 1024) { g_sum1[i] = 0; g_ssq1[i] = 0; }
    for (int i = t; i < C2 * SLOTS; i += 1024) { g_sum2[i] = 0; g_ssq2[i] = 0; }
    for (int i = t; i < C3 * SLOTS; i += 1024) { g_sum3[i] = 0; g_ssq3[i] = 0; }
}

// ---------------- K1: conv1 stats, smem-tiled, 2x2 px/thread ----------------
// grid (24,24), block 256; out tile 32x32, smem 34x34
__global__ __launch_bounds__(256) void k_conv1s(const float* __restrict__ img,
                                                const float* __restrict__ w1) {
    __shared__ float sw[C1 * 9];
    __shared__ float st[34 * 34];
    __shared__ float sred[8 * C1], qred[8 * C1];
    int tid = threadIdx.x, tx = tid & 15, ty = tid >> 4;
    int bx0 = blockIdx.x * 32 - 1, by0 = blockIdx.y * 32 - 1;
    bool edge = (blockIdx.x == 0) | (blockIdx.y == 0) |
                (blockIdx.x == 23) | (blockIdx.y == 23);
    if (edge) {
        for (int i = tid; i < 34 * 34; i += 256) {
            int r = i / 34, c = i - r * 34;
            int yy = by0 + r, xx = bx0 + c;
            st[i] = ((unsigned)yy < HW && (unsigned)xx < HW) ? img[yy * HW + xx] : 0.f;
        }
    } else {
        for (int i = tid; i < 34 * 34; i += 256) {
            int r = i / 34, c = i - r * 34;
            st[i] = img[(by0 + r) * HW + bx0 + c];
        }
    }
    if (tid < C1 * 9) sw[tid] = w1[tid];
    __syncthreads();

    float s[C1], q[C1];
#pragma unroll
    for (int c = 0; c < C1; c++) { s[c] = 0.f; q[c] = 0.f; }

#pragma unroll
    for (int py = 0; py < 2; py++)
#pragma unroll
        for (int px = 0; px < 2; px++) {
            int ry = ty + 16 * py, rx = tx + 16 * px;
            float v[9];
#pragma unroll
            for (int dy = 0; dy < 3; dy++)
#pragma unroll
                for (int dx = 0; dx < 3; dx++)
                    v[dy * 3 + dx] = st[(ry + dy) * 34 + rx + dx];
#pragma unroll
            for (int c = 0; c < C1; c++) {
                float a = 0.f;
#pragma unroll
                for (int k = 0; k < 9; k++) a += v[k] * sw[c * 9 + k];
                s[c] += a; q[c] += a * a;
            }
        }

    int lane = tid & 31, warp = tid >> 5;
    for (int c = 0; c < C1; c++) {
        float ss = s[c], qq = q[c];
        for (int d = 16; d; d >>= 1) {
            ss += __shfl_xor_sync(~0u, ss, d);
            qq += __shfl_xor_sync(~0u, qq, d);
        }
        if (lane == 0) { sred[warp * C1 + c] = ss; qred[warp * C1 + c] = qq; }
    }
    __syncthreads();
    if (tid < C1) {
        float ss = 0, qq = 0;
        for (int w8 = 0; w8 < 8; w8++) { ss += sred[w8 * C1 + tid]; qq += qred[w8 * C1 + tid]; }
        int slot = (blockIdx.y * gridDim.x + blockIdx.x) & (SLOTS - 1);
        atomicAdd(&g_sum1[tid * SLOTS + slot], (double)ss);
        atomicAdd(&g_ssq1[tid * SLOTS + slot], (double)qq);
    }
}

// ---------------- K2: conv1+bn1+conv2 -> raw padded nf2, stats2 ----------------
// grid (12,24,2), block 256; out tile 32x x 16y, 2 x-px/thread, 16 outs per z
__global__ __launch_bounds__(256, 3) void k_conv2f(const float* __restrict__ img,
                                                   const float* __restrict__ w1,
                                                   const float* __restrict__ w2) {
    __shared__ float simg[35 * 67];
    __shared__ float sf1[2][33 * 65];
    __shared__ float sw2[2][16 * 9];
    __shared__ float sw1[C1 * 9];
    __shared__ float sm1[C1], sr1[C1];
    __shared__ float sred[8 * 16], qred[8 * 16];

    int tid = threadIdx.x, tx = tid & 15, ty = tid >> 4;
    int ibx = 64 * blockIdx.x - 1;
    int iby = 32 * blockIdx.y - 1;
    int obase = blockIdx.z * 16;

    bool img_edge = (blockIdx.x == 0) | (blockIdx.y == 0) |
                    (blockIdx.x == 11) | (blockIdx.y == 23);
    bool f1_edge = (blockIdx.x == 0) | (blockIdx.y == 0);

    if (img_edge) {
        for (int i = tid; i < 35 * 67; i += 256) {
            int r = i / 67, c = i - r * 67;
            int yy = iby - 1 + r, xx = ibx - 1 + c;
            simg[i] = ((unsigned)yy < HW && (unsigned)xx < HW) ? img[yy * HW + xx] : 0.f;
        }
    } else {
        for (int i = tid; i < 35 * 67; i += 256) {
            int r = i / 67, c = i - r * 67;
            simg[i] = img[(iby - 1 + r) * HW + ibx - 1 + c];
        }
    }
    if (tid < C1 * 9) sw1[tid] = w1[tid];
    if (tid < C1) {
        double s = 0, q = 0;
        for (int j = 0; j < SLOTS; j++) { s += g_sum1[tid * SLOTS + j]; q += g_ssq1[tid * SLOTS + j]; }
        double m = s / (double)(HW * HW);
        double v = q / (double)(HW * HW) - m * m;
        sm1[tid] = (float)m;
        sr1[tid] = (float)rsqrt(v + 1e-5);
    }
    __syncthreads();

    auto stage = [&](int b, int c1) {
        float m = sm1[c1], rs = sr1[c1];
        const float* wp = &sw1[c1 * 9];
        if (f1_edge) {
            for (int i = tid; i < 33 * 65; i += 256) {
                int rr = i / 65, cc = i - rr * 65;
                int fy = iby + rr, fx = ibx + cc;
                float t = 0.f;
                if (fy >= 0 && fx >= 0) {
                    float a = 0.f;
#pragma unroll
                    for (int dy = 0; dy < 3; dy++)
#pragma unroll
                        for (int dx = 0; dx < 3; dx++)
                            a += simg[(rr + dy) * 67 + cc + dx] * wp[dy * 3 + dx];
                    t = fmaxf((a - m) * rs, 0.f);
                }
                sf1[b][i] = t;
            }
        } else {
            for (int i = tid; i < 33 * 65; i += 256) {
                int rr = i / 65, cc = i - rr * 65;
                float a = 0.f;
#pragma unroll
                for (int dy = 0; dy < 3; dy++)
#pragma unroll
                    for (int dx = 0; dx < 3; dx++)
                        a += simg[(rr + dy) * 67 + cc + dx] * wp[dy * 3 + dx];
                sf1[b][i] = fmaxf((a - m) * rs, 0.f);
            }
        }
        if (tid < 16 * 9)
            sw2[b][tid] = w2[(obase + tid / 9) * (C1 * 9) + c1 * 9 + (tid % 9)];
    };

    float acc0[16], acc1[16];
#pragma unroll
    for (int o = 0; o < 16; o++) { acc0[o] = 0.f; acc1[o] = 0.f; }

    stage(0, 0);
    for (int c1 = 0; c1 < C1; c1++) {
        __syncthreads();
        if (c1 + 1 < C1) stage((c1 + 1) & 1, c1 + 1);

        const float* f = sf1[c1 & 1];
        const float* w = sw2[c1 & 1];
        float v0[9], v1[9];
#pragma unroll
        for (int kh = 0; kh < 3; kh++)
#pragma unroll
            for (int kw = 0; kw < 3; kw++) {
                v0[kh * 3 + kw] = f[(2 * ty + kh) * 65 + 2 * tx + kw];
                v1[kh * 3 + kw] = f[(2 * ty + kh) * 65 + 2 * tx + 32 + kw];
            }
#pragma unroll
        for (int o = 0; o < 16; o++) {
            float a0 = acc0[o], a1 = acc1[o];
#pragma unroll
            for (int k = 0; k < 9; k++) {
                float wf = w[o * 9 + k];
                a0 += v0[k] * wf;
                a1 += v1[k] * wf;
            }
            acc0[o] = a0; acc1[o] = a1;
        }
    }

    int oy = blockIdx.y * 16 + ty, ox = blockIdx.x * 32 + tx;
#pragma unroll
    for (int o = 0; o < 16; o++) {
        float* dst = g_nf2 + (size_t)(obase + o) * NPH * NPW + (size_t)(1 + oy) * NPW + 1;
        dst[ox]      = acc0[o];
        dst[ox + 16] = acc1[o];
    }
    int lane = tid & 31, warp = tid >> 5;
    for (int o = 0; o < 16; o++) {
        float s = acc0[o] + acc1[o];
        float q = acc0[o] * acc0[o] + acc1[o] * acc1[o];
        for (int d = 16; d; d >>= 1) {
            s += __shfl_xor_sync(~0u, s, d);
            q += __shfl_xor_sync(~0u, q, d);
        }
        if (lane == 0) { sred[warp * 16 + o] = s; qred[warp * 16 + o] = q; }
    }
    __syncthreads();
    if (tid < 16) {
        float s = 0, q = 0;
        for (int w8 = 0; w8 < 8; w8++) { s += sred[w8 * 16 + tid]; q += qred[w8 * 16 + tid]; }
        int slot = (blockIdx.y * gridDim.x + blockIdx.x) & (SLOTS - 1);
        atomicAdd(&g_sum2[(obase + tid) * SLOTS + slot], (double)s);
        atomicAdd(&g_ssq2[(obase + tid) * SLOTS + slot], (double)q);
    }
}

// ---------------- bn2: in-place normalize interior of nf2 (float4 RMW) ----------------
// grid (32, 12), block 256
__global__ __launch_bounds__(256) void k_bn2in() {
    int c = blockIdx.x;
    __shared__ float s_m, s_r;
    if (threadIdx.x == 0) {
        double s = 0, q = 0;
        for (int j = 0; j < SLOTS; j++) { s += g_sum2[c * SLOTS + j]; q += g_ssq2[c * SLOTS + j]; }
        double m = s / (double)(H2 * H2);
        double v = q / (double)(H2 * H2) - m * m;
        s_m = (float)m;
        s_r = (float)rsqrt(v + 1e-5);
    }
    __syncthreads();
    float m = s_m, r = s_r;
    // rows 1..384 are contiguous: base covers them linearly as 384*98 float4
    float4* base = (float4*)(g_nf2 + (size_t)c * NPH * NPW + NPW);
    const int total = 384 * (NPW / 4);
    for (int i = blockIdx.y * 256 + threadIdx.x; i < total; i += 12 * 256) {
        int q4 = i % (NPW / 4);
        int pc = q4 * 4;                 // padded col of element 0
        float4 v4 = base[i];
        float o0 = (pc + 0 >= 1 && pc + 0 <= 384) ? fmaxf((v4.x - m) * r, 0.f) : 0.f;
        float o1 = (pc + 1 >= 1 && pc + 1 <= 384) ? fmaxf((v4.y - m) * r, 0.f) : 0.f;
        float o2 = (pc + 2 >= 1 && pc + 2 <= 384) ? fmaxf((v4.z - m) * r, 0.f) : 0.f;
        float o3 = (pc + 3 >= 1 && pc + 3 <= 384) ? fmaxf((v4.w - m) * r, 0.f) : 0.f;
        base[i] = make_float4(o0, o1, o2, o3);
    }
}

// ---------------- K3: conv3 from nf2 (float4 staging), stats3 ----------------
// grid (6,12,4), block 256; out tile 32x x 16y, 2 x-px/thread, 16 outs per z
__global__ __launch_bounds__(256, 3) void k_conv3f(const float* __restrict__ w3) {
    __shared__ float sf[2][33 * 68];
    __shared__ float sw[2][16 * 9];
    __shared__ float sred[8 * 16], qred[8 * 16];

    int tid = threadIdx.x, tx = tid & 15, ty = tid >> 4;
    int colbase = 64 * blockIdx.x;
    int rowbase = 32 * blockIdx.y;
    int obase = blockIdx.z * 16;

    auto stage = [&](int b, int c) {
        const float* src = g_nf2 + (size_t)c * NPH * NPW;
        for (int i = tid; i < 33 * 17; i += 256) {
            int r = i / 17, q4 = i - r * 17;
            const float4* s4 =
                (const float4*)(src + (size_t)(rowbase + r) * NPW + colbase) + q4;
            ((float4*)&sf[b][r * 68])[q4] = *s4;
        }
        if (tid < 16 * 9)
            sw[b][tid] = w3[(obase + tid / 9) * (C2 * 9) + c * 9 + (tid % 9)];
    };

    float acc0[16], acc1[16];
#pragma unroll
    for (int o = 0; o < 16; o++) { acc0[o] = 0.f; acc1[o] = 0.f; }

    stage(0, 0);
    for (int c = 0; c < C2; c++) {
        __syncthreads();
        if (c + 1 < C2) stage((c + 1) & 1, c + 1);

        const float* f = sf[c & 1];
        const float* w = sw[c & 1];
        float v0[9], v1[9];
#pragma unroll
        for (int kh = 0; kh < 3; kh++)
#pragma unroll
            for (int kw = 0; kw < 3; kw++) {
                v0[kh * 3 + kw] = f[(2 * ty + kh) * 68 + 2 * tx + kw];
                v1[kh * 3 + kw] = f[(2 * ty + kh) * 68 + 2 * tx + 32 + kw];
            }
#pragma unroll
        for (int o = 0; o < 16; o++) {
            float a0 = acc0[o], a1 = acc1[o];
#pragma unroll
            for (int k = 0; k < 9; k++) {
                float wf = w[o * 9 + k];
                a0 += v0[k] * wf;
                a1 += v1[k] * wf;
            }
            acc0[o] = a0; acc1[o] = a1;
        }
    }

    int oy = blockIdx.y * 16 + ty, ox = blockIdx.x * 32 + tx;
#pragma unroll
    for (int o = 0; o < 16; o++) {
        g_f3[(size_t)(obase + o) * H3 * H3 + (size_t)oy * H3 + ox]      = acc0[o];
        g_f3[(size_t)(obase + o) * H3 * H3 + (size_t)oy * H3 + ox + 16] = acc1[o];
    }

    int lane = tid & 31, warp = tid >> 5;
    for (int o = 0; o < 16; o++) {
        float s = acc0[o] + acc1[o];
        float q = acc0[o] * acc0[o] + acc1[o] * acc1[o];
        for (int d = 16; d; d >>= 1) {
            s += __shfl_xor_sync(~0u, s, d);
            q += __shfl_xor_sync(~0u, q, d);
        }
        if (lane == 0) { sred[warp * 16 + o] = s; qred[warp * 16 + o] = q; }
    }
    __syncthreads();
    if (tid < 16) {
        float s = 0, q = 0;
        for (int w8 = 0; w8 < 8; w8++) { s += sred[w8 * 16 + tid]; q += qred[w8 * 16 + tid]; }
        int slot = ((blockIdx.z * gridDim.y + blockIdx.y) * gridDim.x + blockIdx.x) & (SLOTS - 1);
        atomicAdd(&g_sum3[(obase + tid) * SLOTS + slot], (double)s);
        atomicAdd(&g_ssq3[(obase + tid) * SLOTS + slot], (double)q);
    }
}

// ---------------- heads: partial dot-products, 8-channel groups ----------------
__global__ __launch_bounds__(256) void k_heads_acc(
    const float* __restrict__ pw, const float* __restrict__ tw,
    const float* __restrict__ shw, const float* __restrict__ scw,
    const float* __restrict__ tiw) {
    int cg = blockIdx.y;
    __shared__ float sm3[8], sr3[8];
    int tid = threadIdx.x;
    if (tid < 8) {
        int c = cg * 8 + tid;
        double s = 0, q = 0;
        for (int j = 0; j < SLOTS; j++) { s += g_sum3[c * SLOTS + j]; q += g_ssq3[c * SLOTS + j]; }
        double m = s / (double)(H3 * H3);
        double v = q / (double)(H3 * H3) - m * m;
        sm3[tid] = (float)m;
        sr3[tid] = (float)rsqrt(v + 1e-5);
    }
    __syncthreads();

    int p = blockIdx.x * 256 + tid;
    int gx = p % NG, gy = p / NG;

    float ap = 0, at = 0, as0 = 0, as1 = 0, asc = 0, ati = 0;
#pragma unroll
    for (int cc = 0; cc < 8; cc++) {
        int c = cg * 8 + cc;
        float m = sm3[cc], r = sr3[cc];
        const float* fc = g_f3 + (size_t)c * H3 * H3 + (size_t)(2 * gy) * H3 + 2 * gx;
#pragma unroll
        for (int kh = 0; kh < 2; kh++)
#pragma unroll
            for (int kw = 0; kw < 2; kw++) {
                float v = fmaxf((fc[kh * H3 + kw] - m) * r, 0.f);
                int wi = c * 4 + kh * 2 + kw;
                ap  += v * pw[wi];
                at  += v * tw[wi];
                as0 += v * shw[wi];
                as1 += v * shw[256 + wi];
                asc += v * scw[wi];
                ati += v * tiw[wi];
            }
    }
    float* part = g_hpart[cg];
    part[0 * NPATCH + p] = ap;
    part[1 * NPATCH + p] = at;
    part[2 * NPATCH + p] = as0;
    part[3 * NPATCH + p] = as1;
    part[4 * NPATCH + p] = asc;
    part[5 * NPATCH + p] = ati;
}

__global__ __launch_bounds__(256) void k_heads_fin(
    const float* __restrict__ pb, const float* __restrict__ tb,
    const float* __restrict__ shb, const float* __restrict__ scb,
    const float* __restrict__ tib) {
    int p = blockIdx.x * 256 + threadIdx.x;
    float a[6] = {0, 0, 0, 0, 0, 0};
#pragma unroll
    for (int g = 0; g < 8; g++)
#pragma unroll
        for (int j = 0; j < 6; j++) a[j] += g_hpart[g][j * NPATCH + p];

    float psi = 3.14159f * tanhf(a[0] + pb[0]);
    float th  = 3.14159f * tanhf(a[1] + tb[0]);
    float s0  = 0.2f * tanhf(a[2] + shb[0]);
    float s1  = 0.2f * tanhf(a[3] + shb[1]);
    float sc  = fminf(fmaxf(1.f + 0.25f * tanhf(a[4] + scb[0]), 0.8f), 1.25f);
    float ti  = fminf(fmaxf(1.f + 0.8f  * tanhf(a[5] + tib[0]), 1.0f), 1.8f);

    float cp = cosf(psi), sp = sinf(psi);
    float ct = cosf(th),  st = sinf(th);
    float M00 = ti * ct, M01 = -ti * st;
    float M10 = st / ti, M11 = ct / ti;
    g_A[p * 4 + 0] = sc * (cp * M00 - sp * M10);
    g_A[p * 4 + 1] = sc * (cp * M01 - sp * M11);
    g_A[p * 4 + 2] = sc * (sp * M00 + cp * M10);
    g_A[p * 4 + 3] = sc * (sp * M01 + cp * M11);
    g_shift[p]          = s0;
    g_shift[NPATCH + p] = s1;
}

// ---------------- assemble (shift cross-channel reindex) + aff ----------------
__global__ void k_assemble(float* __restrict__ out) {
    int n = blockIdx.x * blockDim.x + threadIdx.x;
    if (n >= NPATCH) return;
    float t0 = g_A[n * 4 + 0], t1 = g_A[n * 4 + 1];
    float t3 = g_A[n * 4 + 2], t4 = g_A[n * 4 + 3];
    float t2 = g_shift[2 * n];
    float t5 = g_shift[2 * n + 1];
    g_trans[n * 6 + 0] = t0; g_trans[n * 6 + 1] = t1; g_trans[n * 6 + 2] = t2;
    g_trans[n * 6 + 3] = t3; g_trans[n * 6 + 4] = t4; g_trans[n * 6 + 5] = t5;

    float cx = 4.f + 8.f * (float)(n % NG);
    float cy = 4.f + 8.f * (float)(n / NG);
    float* a = out + (size_t)NPATCH * 1024 + (size_t)n * 6;
    a[0] = 32.f * t0; a[1] = 32.f * t1; a[2] = cx + 32.f * t2;
    a[3] = 32.f * t3; a[4] = 32.f * t4; a[5] = cy + 32.f * t5;
}

// ---------------- bilinear sampler: 256 thr, 4 px/thread, float4 store ----------------
__global__ __launch_bounds__(256) void k_sample(const float* __restrict__ img,
                                                float* __restrict__ out) {
    int n = blockIdx.x;
    __shared__ float t[6];
    if (threadIdx.x < 6) t[threadIdx.x] = g_trans[n * 6 + threadIdx.x];
    __syncthreads();
    float t0 = t[0], t1 = t[1], t2 = t[2], t3 = t[3], t4 = t[4], t5 = t[5];

    int p4 = threadIdx.x * 4;
    int h = p4 >> 5, w0 = p4 & 31;
    float Y = ((float)h + 0.5f) * (2.f / 32.f) - 1.f;
    int bx = (n % NG) * 8 - PADO;
    int by = (n / NG) * 8 - PADO;

    auto g = [&](int yy, int xx) -> float {
        if ((unsigned)yy >= GPS || (unsigned)xx >= GPS) return 0.f;
        int ir = by + yy, ic = bx + xx;
        if ((unsigned)ir >= HW || (unsigned)ic >= HW) return 0.f;
        return img[(size_t)ir * HW + ic];
    };

    float res[4];
#pragma unroll
    for (int e = 0; e < 4; e++) {
        float X = ((float)(w0 + e) + 0.5f) * (2.f / 32.f) - 1.f;
        float gx = (X * t0 + Y * t1 + t2) / 4.5f;
        float gy = (X * t3 + Y * t4 + t5) / 4.5f;
        float ix = ((gx + 1.f) * 144.f - 1.f) * 0.5f;
        float iy = ((gy + 1.f) * 144.f - 1.f) * 0.5f;
        float x0f = floorf(ix), y0f = floorf(iy);
        float wx = ix - x0f, wy = iy - y0f;
        int x0 = (int)x0f, y0 = (int)y0f;
        res[e] = (1.f - wy) * ((1.f - wx) * g(y0, x0)     + wx * g(y0, x0 + 1)) +
                 wy        * ((1.f - wx) * g(y0 + 1, x0) + wx * g(y0 + 1, x0 + 1));
    }
    *(float4*)(out + (size_t)n * 1024 + p4) = make_float4(res[0], res[1], res[2], res[3]);
}

// ---------------- launch ----------------
extern "C" void kernel_launch(void* const* d_in, const int* in_sizes, int n_in,
                              void* d_out, int out_size) {
    const float* img = (const float*)d_in[0];
    const float* w1  = (const float*)d_in[1];
    const float* w2  = (const float*)d_in[2];
    const float* w3  = (const float*)d_in[3];
    const float* pw  = (const float*)d_in[4];
    const float* pb  = (const float*)d_in[5];
    const float* tw  = (const float*)d_in[6];
    const float* tb  = (const float*)d_in[7];
    const float* shw = (const float*)d_in[8];
    const float* shb = (const float*)d_in[9];
    const float* scw = (const float*)d_in[10];
    const float* scb = (const float*)d_in[11];
    const float* tiw = (const float*)d_in[12];
    const float* tib = (const float*)d_in[13];
    float* out = (float*)d_out;

    k_zero_stats<<<1, 1024>>>();
    k_conv1s<<<dim3(24, 24), 256>>>(img, w1);
    k_conv2f<<<dim3(12, 24, 2), 256>>>(img, w1, w2);
    k_bn2in<<<dim3(32, 12), 256>>>();
    k_conv3f<<<dim3(6, 12, 4), 256>>>(w3);
    k_heads_acc<<<dim3(36, 8), 256>>>(pw, tw, shw, scw, tiw);
    k_heads_fin<<<36, 256>>>(pb, tb, shb, scb, tib);
    k_assemble<<<36, 256>>>(out);
    k_sample<<<NPATCH, 256>>>(img, out);
}

// round 8
// speedup vs baseline: 1.4890x; 1.0080x over previous
#include <cuda_runtime.h>
#include <math.h>

// ---------------- constants ----------------
#define HW      768
#define C1      16
#define C2      32
#define C3      64
#define H2      384
#define H3      192
#define NG      96
#define NPATCH  9216
#define GPS     144
#define PADO    68
#define SLOTS   32
// padded RAW f2: [C2][386][392], 1-px halo (zeros); BN fused into conv3 staging
#define NPH     386
#define NPW     392

// ---------------- device scratch ----------------
__device__ double g_sum1[C1 * SLOTS], g_ssq1[C1 * SLOTS];
__device__ double g_sum2[C2 * SLOTS], g_ssq2[C2 * SLOTS];
__device__ double g_sum3[C3 * SLOTS], g_ssq3[C3 * SLOTS];
__device__ float  g_nf2[C2 * NPH * NPW];
__device__ float  g_f3[C3 * H3 * H3];
__device__ float  g_hpart[8][6 * NPATCH];
__device__ float  g_A[NPATCH * 4];
__device__ float  g_shift[2 * NPATCH];
__device__ float  g_trans[NPATCH * 6];

// ---------------- zero stats ----------------
__global__ void k_zero_stats() {
    int t = threadIdx.x;
    for (int i = t; i < C1 * SLOTS; i += 1024) { g_sum1[i] = 0; g_ssq1[i] = 0; }
    for (int i = t; i < C2 * SLOTS; i += 1024) { g_sum2[i] = 0; g_ssq2[i] = 0; }
    for (int i = t; i < C3 * SLOTS; i += 1024) { g_sum3[i] = 0; g_ssq3[i] = 0; }
}

// ---------------- K1: conv1 stats, smem-tiled, 2x2 px/thread ----------------
__global__ __launch_bounds__(256) void k_conv1s(const float* __restrict__ img,
                                                const float* __restrict__ w1) {
    __shared__ float sw[C1 * 9];
    __shared__ float st[34 * 34];
    __shared__ float sred[8 * C1], qred[8 * C1];
    int tid = threadIdx.x, tx = tid & 15, ty = tid >> 4;
    int bx0 = blockIdx.x * 32 - 1, by0 = blockIdx.y * 32 - 1;
    bool edge = (blockIdx.x == 0) | (blockIdx.y == 0) |
                (blockIdx.x == 23) | (blockIdx.y == 23);
    if (edge) {
        for (int i = tid; i < 34 * 34; i += 256) {
            int r = i / 34, c = i - r * 34;
            int yy = by0 + r, xx = bx0 + c;
            st[i] = ((unsigned)yy < HW && (unsigned)xx < HW) ? img[yy * HW + xx] : 0.f;
        }
    } else {
        for (int i = tid; i < 34 * 34; i += 256) {
            int r = i / 34, c = i - r * 34;
            st[i] = img[(by0 + r) * HW + bx0 + c];
        }
    }
    if (tid < C1 * 9) sw[tid] = w1[tid];
    __syncthreads();

    float s[C1], q[C1];
#pragma unroll
    for (int c = 0; c < C1; c++) { s[c] = 0.f; q[c] = 0.f; }

#pragma unroll
    for (int py = 0; py < 2; py++)
#pragma unroll
        for (int px = 0; px < 2; px++) {
            int ry = ty + 16 * py, rx = tx + 16 * px;
            float v[9];
#pragma unroll
            for (int dy = 0; dy < 3; dy++)
#pragma unroll
                for (int dx = 0; dx < 3; dx++)
                    v[dy * 3 + dx] = st[(ry + dy) * 34 + rx + dx];
#pragma unroll
            for (int c = 0; c < C1; c++) {
                float a = 0.f;
#pragma unroll
                for (int k = 0; k < 9; k++) a += v[k] * sw[c * 9 + k];
                s[c] += a; q[c] += a * a;
            }
        }

    int lane = tid & 31, warp = tid >> 5;
    for (int c = 0; c < C1; c++) {
        float ss = s[c], qq = q[c];
        for (int d = 16; d; d >>= 1) {
            ss += __shfl_xor_sync(~0u, ss, d);
            qq += __shfl_xor_sync(~0u, qq, d);
        }
        if (lane == 0) { sred[warp * C1 + c] = ss; qred[warp * C1 + c] = qq; }
    }
    __syncthreads();
    if (tid < C1) {
        float ss = 0, qq = 0;
        for (int w8 = 0; w8 < 8; w8++) { ss += sred[w8 * C1 + tid]; qq += qred[w8 * C1 + tid]; }
        int slot = (blockIdx.y * gridDim.x + blockIdx.x) & (SLOTS - 1);
        atomicAdd(&g_sum1[tid * SLOTS + slot], (double)ss);
        atomicAdd(&g_ssq1[tid * SLOTS + slot], (double)qq);
    }
}

// ---------------- K2: conv1+bn1+conv2 -> raw padded nf2, stats2 ----------------
// grid (12,24,2), block 256; out tile 32x x 16y, 2 x-px/thread, 16 outs per z
__global__ __launch_bounds__(256, 3) void k_conv2f(const float* __restrict__ img,
                                                   const float* __restrict__ w1,
                                                   const float* __restrict__ w2) {
    __shared__ float simg[35 * 67];
    __shared__ float sf1[2][33 * 65];
    __shared__ float sw2[2][16 * 9];
    __shared__ float sw1[C1 * 9];
    __shared__ float sm1[C1], sr1[C1];
    __shared__ float sred[8 * 16], qred[8 * 16];

    int tid = threadIdx.x, tx = tid & 15, ty = tid >> 4;
    int ibx = 64 * blockIdx.x - 1;
    int iby = 32 * blockIdx.y - 1;
    int obase = blockIdx.z * 16;

    bool img_edge = (blockIdx.x == 0) | (blockIdx.y == 0) |
                    (blockIdx.x == 11) | (blockIdx.y == 23);
    bool f1_edge = (blockIdx.x == 0) | (blockIdx.y == 0);

    if (img_edge) {
        for (int i = tid; i < 35 * 67; i += 256) {
            int r = i / 67, c = i - r * 67;
            int yy = iby - 1 + r, xx = ibx - 1 + c;
            simg[i] = ((unsigned)yy < HW && (unsigned)xx < HW) ? img[yy * HW + xx] : 0.f;
        }
    } else {
        for (int i = tid; i < 35 * 67; i += 256) {
            int r = i / 67, c = i - r * 67;
            simg[i] = img[(iby - 1 + r) * HW + ibx - 1 + c];
        }
    }
    if (tid < C1 * 9) sw1[tid] = w1[tid];
    if (tid < C1) {
        double s = 0, q = 0;
        for (int j = 0; j < SLOTS; j++) { s += g_sum1[tid * SLOTS + j]; q += g_ssq1[tid * SLOTS + j]; }
        double m = s / (double)(HW * HW);
        double v = q / (double)(HW * HW) - m * m;
        sm1[tid] = (float)m;
        sr1[tid] = (float)rsqrt(v + 1e-5);
    }
    __syncthreads();

    auto stage = [&](int b, int c1) {
        float m = sm1[c1], rs = sr1[c1];
        const float* wp = &sw1[c1 * 9];
        if (f1_edge) {
            for (int i = tid; i < 33 * 65; i += 256) {
                int rr = i / 65, cc = i - rr * 65;
                int fy = iby + rr, fx = ibx + cc;
                float t = 0.f;
                if (fy >= 0 && fx >= 0) {
                    float a = 0.f;
#pragma unroll
                    for (int dy = 0; dy < 3; dy++)
#pragma unroll
                        for (int dx = 0; dx < 3; dx++)
                            a += simg[(rr + dy) * 67 + cc + dx] * wp[dy * 3 + dx];
                    t = fmaxf((a - m) * rs, 0.f);
                }
                sf1[b][i] = t;
            }
        } else {
            for (int i = tid; i < 33 * 65; i += 256) {
                int rr = i / 65, cc = i - rr * 65;
                float a = 0.f;
#pragma unroll
                for (int dy = 0; dy < 3; dy++)
#pragma unroll
                    for (int dx = 0; dx < 3; dx++)
                        a += simg[(rr + dy) * 67 + cc + dx] * wp[dy * 3 + dx];
                sf1[b][i] = fmaxf((a - m) * rs, 0.f);
            }
        }
        if (tid < 16 * 9)
            sw2[b][tid] = w2[(obase + tid / 9) * (C1 * 9) + c1 * 9 + (tid % 9)];
    };

    float acc0[16], acc1[16];
#pragma unroll
    for (int o = 0; o < 16; o++) { acc0[o] = 0.f; acc1[o] = 0.f; }

    stage(0, 0);
    for (int c1 = 0; c1 < C1; c1++) {
        __syncthreads();
        if (c1 + 1 < C1) stage((c1 + 1) & 1, c1 + 1);

        const float* f = sf1[c1 & 1];
        const float* w = sw2[c1 & 1];
        float v0[9], v1[9];
#pragma unroll
        for (int kh = 0; kh < 3; kh++)
#pragma unroll
            for (int kw = 0; kw < 3; kw++) {
                v0[kh * 3 + kw] = f[(2 * ty + kh) * 65 + 2 * tx + kw];
                v1[kh * 3 + kw] = f[(2 * ty + kh) * 65 + 2 * tx + 32 + kw];
            }
#pragma unroll
        for (int o = 0; o < 16; o++) {
            float a0 = acc0[o], a1 = acc1[o];
#pragma unroll
            for (int k = 0; k < 9; k++) {
                float wf = w[o * 9 + k];
                a0 += v0[k] * wf;
                a1 += v1[k] * wf;
            }
            acc0[o] = a0; acc1[o] = a1;
        }
    }

    int oy = blockIdx.y * 16 + ty, ox = blockIdx.x * 32 + tx;
#pragma unroll
    for (int o = 0; o < 16; o++) {
        float* dst = g_nf2 + (size_t)(obase + o) * NPH * NPW + (size_t)(1 + oy) * NPW + 1;
        dst[ox]      = acc0[o];
        dst[ox + 16] = acc1[o];
    }
    int lane = tid & 31, warp = tid >> 5;
    for (int o = 0; o < 16; o++) {
        float s = acc0[o] + acc1[o];
        float q = acc0[o] * acc0[o] + acc1[o] * acc1[o];
        for (int d = 16; d; d >>= 1) {
            s += __shfl_xor_sync(~0u, s, d);
            q += __shfl_xor_sync(~0u, q, d);
        }
        if (lane == 0) { sred[warp * 16 + o] = s; qred[warp * 16 + o] = q; }
    }
    __syncthreads();
    if (tid < 16) {
        float s = 0, q = 0;
        for (int w8 = 0; w8 < 8; w8++) { s += sred[w8 * 16 + tid]; q += qred[w8 * 16 + tid]; }
        int slot = (blockIdx.y * gridDim.x + blockIdx.x) & (SLOTS - 1);
        atomicAdd(&g_sum2[(obase + tid) * SLOTS + slot], (double)s);
        atomicAdd(&g_ssq2[(obase + tid) * SLOTS + slot], (double)q);
    }
}

// ---------------- K3: conv3 with fused BN2 in staging, stats3 ----------------
// grid (6,12,4), block 256; out tile 32x x 16y, 2 x-px/thread, 16 outs per z
__global__ __launch_bounds__(256, 3) void k_conv3f(const float* __restrict__ w3) {
    __shared__ float sf[2][33 * 68];
    __shared__ float sw[2][16 * 9];
    __shared__ float sm2[C2], sr2[C2];
    __shared__ float sred[8 * 16], qred[8 * 16];

    int tid = threadIdx.x, tx = tid & 15, ty = tid >> 4;
    int colbase = 64 * blockIdx.x;
    int rowbase = 32 * blockIdx.y;
    int obase = blockIdx.z * 16;
    bool left = (blockIdx.x == 0), top = (blockIdx.y == 0);

    if (tid < C2) {
        double s = 0, q = 0;
        for (int j = 0; j < SLOTS; j++) { s += g_sum2[tid * SLOTS + j]; q += g_ssq2[tid * SLOTS + j]; }
        double m = s / (double)(H2 * H2);
        double v = q / (double)(H2 * H2) - m * m;
        sm2[tid] = (float)m;
        sr2[tid] = (float)rsqrt(v + 1e-5);
    }
    __syncthreads();  // stats ready before first stage reads them

    auto stage = [&](int b, int c) {
        const float* src = g_nf2 + (size_t)c * NPH * NPW;
        float m = sm2[c], rs = sr2[c];
        for (int i = tid; i < 33 * 17; i += 256) {
            int r = i / 17, q4 = i - r * 17;
            float4 v4 = *((const float4*)(src + (size_t)(rowbase + r) * NPW + colbase) + q4);
            float o0 = fmaxf((v4.x - m) * rs, 0.f);
            float o1 = fmaxf((v4.y - m) * rs, 0.f);
            float o2 = fmaxf((v4.z - m) * rs, 0.f);
            float o3 = fmaxf((v4.w - m) * rs, 0.f);
            // halo corrections: padded row 0 / padded col 0 must be literal 0
            if (top && r == 0) { o0 = o1 = o2 = o3 = 0.f; }
            if (left && q4 == 0) o0 = 0.f;
            ((float4*)&sf[b][r * 68])[q4] = make_float4(o0, o1, o2, o3);
        }
        if (tid < 16 * 9)
            sw[b][tid] = w3[(obase + tid / 9) * (C2 * 9) + c * 9 + (tid % 9)];
    };

    float acc0[16], acc1[16];
#pragma unroll
    for (int o = 0; o < 16; o++) { acc0[o] = 0.f; acc1[o] = 0.f; }

    stage(0, 0);
    for (int c = 0; c < C2; c++) {
        __syncthreads();
        if (c + 1 < C2) stage((c + 1) & 1, c + 1);

        const float* f = sf[c & 1];
        const float* w = sw[c & 1];
        float v0[9], v1[9];
#pragma unroll
        for (int kh = 0; kh < 3; kh++)
#pragma unroll
            for (int kw = 0; kw < 3; kw++) {
                v0[kh * 3 + kw] = f[(2 * ty + kh) * 68 + 2 * tx + kw];
                v1[kh * 3 + kw] = f[(2 * ty + kh) * 68 + 2 * tx + 32 + kw];
            }
#pragma unroll
        for (int o = 0; o < 16; o++) {
            float a0 = acc0[o], a1 = acc1[o];
#pragma unroll
            for (int k = 0; k < 9; k++) {
                float wf = w[o * 9 + k];
                a0 += v0[k] * wf;
                a1 += v1[k] * wf;
            }
            acc0[o] = a0; acc1[o] = a1;
        }
    }

    int oy = blockIdx.y * 16 + ty, ox = blockIdx.x * 32 + tx;
#pragma unroll
    for (int o = 0; o < 16; o++) {
        g_f3[(size_t)(obase + o) * H3 * H3 + (size_t)oy * H3 + ox]      = acc0[o];
        g_f3[(size_t)(obase + o) * H3 * H3 + (size_t)oy * H3 + ox + 16] = acc1[o];
    }

    int lane = tid & 31, warp = tid >> 5;
    for (int o = 0; o < 16; o++) {
        float s = acc0[o] + acc1[o];
        float q = acc0[o] * acc0[o] + acc1[o] * acc1[o];
        for (int d = 16; d; d >>= 1) {
            s += __shfl_xor_sync(~0u, s, d);
            q += __shfl_xor_sync(~0u, q, d);
        }
        if (lane == 0) { sred[warp * 16 + o] = s; qred[warp * 16 + o] = q; }
    }
    __syncthreads();
    if (tid < 16) {
        float s = 0, q = 0;
        for (int w8 = 0; w8 < 8; w8++) { s += sred[w8 * 16 + tid]; q += qred[w8 * 16 + tid]; }
        int slot = ((blockIdx.z * gridDim.y + blockIdx.y) * gridDim.x + blockIdx.x) & (SLOTS - 1);
        atomicAdd(&g_sum3[(obase + tid) * SLOTS + slot], (double)s);
        atomicAdd(&g_ssq3[(obase + tid) * SLOTS + slot], (double)q);
    }
}

// ---------------- heads: partial dot-products, 8-channel groups ----------------
__global__ __launch_bounds__(256) void k_heads_acc(
    const float* __restrict__ pw, const float* __restrict__ tw,
    const float* __restrict__ shw, const float* __restrict__ scw,
    const float* __restrict__ tiw) {
    int cg = blockIdx.y;
    __shared__ float sm3[8], sr3[8];
    int tid = threadIdx.x;
    if (tid < 8) {
        int c = cg * 8 + tid;
        double s = 0, q = 0;
        for (int j = 0; j < SLOTS; j++) { s += g_sum3[c * SLOTS + j]; q += g_ssq3[c * SLOTS + j]; }
        double m = s / (double)(H3 * H3);
        double v = q / (double)(H3 * H3) - m * m;
        sm3[tid] = (float)m;
        sr3[tid] = (float)rsqrt(v + 1e-5);
    }
    __syncthreads();

    int p = blockIdx.x * 256 + tid;
    int gx = p % NG, gy = p / NG;

    float ap = 0, at = 0, as0 = 0, as1 = 0, asc = 0, ati = 0;
#pragma unroll
    for (int cc = 0; cc < 8; cc++) {
        int c = cg * 8 + cc;
        float m = sm3[cc], r = sr3[cc];
        const float* fc = g_f3 + (size_t)c * H3 * H3 + (size_t)(2 * gy) * H3 + 2 * gx;
#pragma unroll
        for (int kh = 0; kh < 2; kh++)
#pragma unroll
            for (int kw = 0; kw < 2; kw++) {
                float v = fmaxf((fc[kh * H3 + kw] - m) * r, 0.f);
                int wi = c * 4 + kh * 2 + kw;
                ap  += v * pw[wi];
                at  += v * tw[wi];
                as0 += v * shw[wi];
                as1 += v * shw[256 + wi];
                asc += v * scw[wi];
                ati += v * tiw[wi];
            }
    }
    float* part = g_hpart[cg];
    part[0 * NPATCH + p] = ap;
    part[1 * NPATCH + p] = at;
    part[2 * NPATCH + p] = as0;
    part[3 * NPATCH + p] = as1;
    part[4 * NPATCH + p] = asc;
    part[5 * NPATCH + p] = ati;
}

__global__ __launch_bounds__(256) void k_heads_fin(
    const float* __restrict__ pb, const float* __restrict__ tb,
    const float* __restrict__ shb, const float* __restrict__ scb,
    const float* __restrict__ tib) {
    int p = blockIdx.x * 256 + threadIdx.x;
    float a[6] = {0, 0, 0, 0, 0, 0};
#pragma unroll
    for (int g = 0; g < 8; g++)
#pragma unroll
        for (int j = 0; j < 6; j++) a[j] += g_hpart[g][j * NPATCH + p];

    float psi = 3.14159f * tanhf(a[0] + pb[0]);
    float th  = 3.14159f * tanhf(a[1] + tb[0]);
    float s0  = 0.2f * tanhf(a[2] + shb[0]);
    float s1  = 0.2f * tanhf(a[3] + shb[1]);
    float sc  = fminf(fmaxf(1.f + 0.25f * tanhf(a[4] + scb[0]), 0.8f), 1.25f);
    float ti  = fminf(fmaxf(1.f + 0.8f  * tanhf(a[5] + tib[0]), 1.0f), 1.8f);

    float cp = cosf(psi), sp = sinf(psi);
    float ct = cosf(th),  st = sinf(th);
    float M00 = ti * ct, M01 = -ti * st;
    float M10 = st / ti, M11 = ct / ti;
    g_A[p * 4 + 0] = sc * (cp * M00 - sp * M10);
    g_A[p * 4 + 1] = sc * (cp * M01 - sp * M11);
    g_A[p * 4 + 2] = sc * (sp * M00 + cp * M10);
    g_A[p * 4 + 3] = sc * (sp * M01 + cp * M11);
    g_shift[p]          = s0;
    g_shift[NPATCH + p] = s1;
}

// ---------------- assemble (shift cross-channel reindex) + aff ----------------
__global__ void k_assemble(float* __restrict__ out) {
    int n = blockIdx.x * blockDim.x + threadIdx.x;
    if (n >= NPATCH) return;
    float t0 = g_A[n * 4 + 0], t1 = g_A[n * 4 + 1];
    float t3 = g_A[n * 4 + 2], t4 = g_A[n * 4 + 3];
    float t2 = g_shift[2 * n];
    float t5 = g_shift[2 * n + 1];
    g_trans[n * 6 + 0] = t0; g_trans[n * 6 + 1] = t1; g_trans[n * 6 + 2] = t2;
    g_trans[n * 6 + 3] = t3; g_trans[n * 6 + 4] = t4; g_trans[n * 6 + 5] = t5;

    float cx = 4.f + 8.f * (float)(n % NG);
    float cy = 4.f + 8.f * (float)(n / NG);
    float* a = out + (size_t)NPATCH * 1024 + (size_t)n * 6;
    a[0] = 32.f * t0; a[1] = 32.f * t1; a[2] = cx + 32.f * t2;
    a[3] = 32.f * t3; a[4] = 32.f * t4; a[5] = cy + 32.f * t5;
}

// ---------------- bilinear sampler: 256 thr, 4 px/thread, float4 store ----------------
__global__ __launch_bounds__(256) void k_sample(const float* __restrict__ img,
                                                float* __restrict__ out) {
    int n = blockIdx.x;
    __shared__ float t[6];
    if (threadIdx.x < 6) t[threadIdx.x] = g_trans[n * 6 + threadIdx.x];
    __syncthreads();
    float t0 = t[0], t1 = t[1], t2 = t[2], t3 = t[3], t4 = t[4], t5 = t[5];

    int p4 = threadIdx.x * 4;
    int h = p4 >> 5, w0 = p4 & 31;
    float Y = ((float)h + 0.5f) * (2.f / 32.f) - 1.f;
    int bx = (n % NG) * 8 - PADO;
    int by = (n / NG) * 8 - PADO;

    auto g = [&](int yy, int xx) -> float {
        if ((unsigned)yy >= GPS || (unsigned)xx >= GPS) return 0.f;
        int ir = by + yy, ic = bx + xx;
        if ((unsigned)ir >= HW || (unsigned)ic >= HW) return 0.f;
        return img[(size_t)ir * HW + ic];
    };

    float res[4];
#pragma unroll
    for (int e = 0; e < 4; e++) {
        float X = ((float)(w0 + e) + 0.5f) * (2.f / 32.f) - 1.f;
        float gx = (X * t0 + Y * t1 + t2) / 4.5f;
        float gy = (X * t3 + Y * t4 + t5) / 4.5f;
        float ix = ((gx + 1.f) * 144.f - 1.f) * 0.5f;
        float iy = ((gy + 1.f) * 144.f - 1.f) * 0.5f;
        float x0f = floorf(ix), y0f = floorf(iy);
        float wx = ix - x0f, wy = iy - y0f;
        int x0 = (int)x0f, y0 = (int)y0f;
        res[e] = (1.f - wy) * ((1.f - wx) * g(y0, x0)     + wx * g(y0, x0 + 1)) +
                 wy        * ((1.f - wx) * g(y0 + 1, x0) + wx * g(y0 + 1, x0 + 1));
    }
    *(float4*)(out + (size_t)n * 1024 + p4) = make_float4(res[0], res[1], res[2], res[3]);
}

// ---------------- launch ----------------
extern "C" void kernel_launch(void* const* d_in, const int* in_sizes, int n_in,
                              void* d_out, int out_size) {
    const float* img = (const float*)d_in[0];
    const float* w1  = (const float*)d_in[1];
    const float* w2  = (const float*)d_in[2];
    const float* w3  = (const float*)d_in[3];
    const float* pw  = (const float*)d_in[4];
    const float* pb  = (const float*)d_in[5];
    const float* tw  = (const float*)d_in[6];
    const float* tb  = (const float*)d_in[7];
    const float* shw = (const float*)d_in[8];
    const float* shb = (const float*)d_in[9];
    const float* scw = (const float*)d_in[10];
    const float* scb = (const float*)d_in[11];
    const float* tiw = (const float*)d_in[12];
    const float* tib = (const float*)d_in[13];
    float* out = (float*)d_out;

    k_zero_stats<<<1, 1024>>>();
    k_conv1s<<<dim3(24, 24), 256>>>(img, w1);
    k_conv2f<<<dim3(12, 24, 2), 256>>>(img, w1, w2);
    k_conv3f<<<dim3(6, 12, 4), 256>>>(w3);
    k_heads_acc<<<dim3(36, 8), 256>>>(pw, tw, shw, scw, tiw);
    k_heads_fin<<<36, 256>>>(pb, tb, shb, scb, tib);
    k_assemble<<<36, 256>>>(out);
    k_sample<<<NPATCH, 256>>>(img, out);
}

// round 10
// speedup vs baseline: 1.5641x; 1.0504x over previous
#include <cuda_runtime.h>
#include <math.h>

// ---------------- constants ----------------
#define HW      768
#define C1      16
#define C2      32
#define C3      64
#define H2      384
#define H3      192
#define NG      96
#define NPATCH  9216
#define GPS     144
#define PADO    68
#define SLOTS   32
// padded RAW f1: [C1][770][776], top/left halo only is ever read
#define NPH1    770
#define NPW1    776
// padded RAW f2: [C2][386][392]
#define NPH     386
#define NPW     392

// ---------------- device scratch ----------------
__device__ double g_sum1[C1 * SLOTS], g_ssq1[C1 * SLOTS];
__device__ double g_sum2[C2 * SLOTS], g_ssq2[C2 * SLOTS];
__device__ double g_sum3[C3 * SLOTS], g_ssq3[C3 * SLOTS];
__device__ float  g_nf1[C1 * NPH1 * NPW1];
__device__ float  g_nf2[C2 * NPH * NPW];
__device__ float  g_f3[C3 * H3 * H3];
__device__ float  g_hpart[8][6 * NPATCH];
__device__ float  g_A[NPATCH * 4];
__device__ float  g_shift[2 * NPATCH];
__device__ float  g_trans[NPATCH * 6];

// ---------------- zero stats ----------------
__global__ void k_zero_stats() {
    int t = threadIdx.x;
    for (int i = t; i < C1 * SLOTS; i += 1024) { g_sum1[i] = 0; g_ssq1[i] = 0; }
    for (int i = t; i < C2 * SLOTS; i += 1024) { g_sum2[i] = 0; g_ssq2[i] = 0; }
    for (int i = t; i < C3 * SLOTS; i += 1024) { g_sum3[i] = 0; g_ssq3[i] = 0; }
}

// ---------------- K1: conv1 stats + raw padded f1 store ----------------
__global__ __launch_bounds__(256) void k_conv1s(const float* __restrict__ img,
                                                const float* __restrict__ w1) {
    __shared__ float sw[C1 * 9];
    __shared__ float st[34 * 34];
    __shared__ float sred[8 * C1], qred[8 * C1];
    int tid = threadIdx.x, tx = tid & 15, ty = tid >> 4;
    int bx0 = blockIdx.x * 32 - 1, by0 = blockIdx.y * 32 - 1;
    bool edge = (blockIdx.x == 0) | (blockIdx.y == 0) |
                (blockIdx.x == 23) | (blockIdx.y == 23);
    if (edge) {
        for (int i = tid; i < 34 * 34; i += 256) {
            int r = i / 34, c = i - r * 34;
            int yy = by0 + r, xx = bx0 + c;
            st[i] = ((unsigned)yy < HW && (unsigned)xx < HW) ? img[yy * HW + xx] : 0.f;
        }
    } else {
        for (int i = tid; i < 34 * 34; i += 256) {
            int r = i / 34, c = i - r * 34;
            st[i] = img[(by0 + r) * HW + bx0 + c];
        }
    }
    if (tid < C1 * 9) sw[tid] = w1[tid];
    __syncthreads();

    float s[C1], q[C1];
#pragma unroll
    for (int c = 0; c < C1; c++) { s[c] = 0.f; q[c] = 0.f; }

#pragma unroll
    for (int py = 0; py < 2; py++)
#pragma unroll
        for (int px = 0; px < 2; px++) {
            int ry = ty + 16 * py, rx = tx + 16 * px;
            int x = blockIdx.x * 32 + rx, y = blockIdx.y * 32 + ry;
            float v[9];
#pragma unroll
            for (int dy = 0; dy < 3; dy++)
#pragma unroll
                for (int dx = 0; dx < 3; dx++)
                    v[dy * 3 + dx] = st[(ry + dy) * 34 + rx + dx];
#pragma unroll
            for (int c = 0; c < C1; c++) {
                float a = 0.f;
#pragma unroll
                for (int k = 0; k < 9; k++) a += v[k] * sw[c * 9 + k];
                s[c] += a; q[c] += a * a;
                g_nf1[(size_t)c * NPH1 * NPW1 + (size_t)(y + 1) * NPW1 + (x + 1)] = a;
            }
        }

    int lane = tid & 31, warp = tid >> 5;
    for (int c = 0; c < C1; c++) {
        float ss = s[c], qq = q[c];
        for (int d = 16; d; d >>= 1) {
            ss += __shfl_xor_sync(~0u, ss, d);
            qq += __shfl_xor_sync(~0u, qq, d);
        }
        if (lane == 0) { sred[warp * C1 + c] = ss; qred[warp * C1 + c] = qq; }
    }
    __syncthreads();
    if (tid < C1) {
        float ss = 0, qq = 0;
        for (int w8 = 0; w8 < 8; w8++) { ss += sred[w8 * C1 + tid]; qq += qred[w8 * C1 + tid]; }
        int slot = (blockIdx.y * gridDim.x + blockIdx.x) & (SLOTS - 1);
        atomicAdd(&g_sum1[tid * SLOTS + slot], (double)ss);
        atomicAdd(&g_ssq1[tid * SLOTS + slot], (double)qq);
    }
}

// ---------------- K2: conv2 from nf1 (fused bn1 staging) -> raw nf2, stats2 ----
// grid (12,24,2), block 256; out tile 32x x 16y, 2 x-px/thread, 16 outs per z
__global__ __launch_bounds__(256, 3) void k_conv2f(const float* __restrict__ w2) {
    __shared__ __align__(16) float sf[2][33 * 68];
    __shared__ __align__(16) float sw[2][16 * 12];
    __shared__ float sm1[C1], sr1[C1];
    __shared__ float sred[8 * 16], qred[8 * 16];

    int tid = threadIdx.x, tx = tid & 15, ty = tid >> 4;
    int colbase = 64 * blockIdx.x;
    int rowbase = 32 * blockIdx.y;
    int obase = blockIdx.z * 16;
    bool left = (blockIdx.x == 0), top = (blockIdx.y == 0);

    if (tid < C1) {
        double s = 0, q = 0;
        for (int j = 0; j < SLOTS; j++) { s += g_sum1[tid * SLOTS + j]; q += g_ssq1[tid * SLOTS + j]; }
        double m = s / (double)(HW * HW);
        double v = q / (double)(HW * HW) - m * m;
        sm1[tid] = (float)m;
        sr1[tid] = (float)rsqrt(v + 1e-5);
    }
    __syncthreads();

    auto stage = [&](int b, int c1) {
        const float* src = g_nf1 + (size_t)c1 * NPH1 * NPW1;
        float m = sm1[c1], rs = sr1[c1];
        for (int i = tid; i < 33 * 17; i += 256) {
            int r = i / 17, q4 = i - r * 17;
            float4 v4 = *((const float4*)(src + (size_t)(rowbase + r) * NPW1 + colbase) + q4);
            float o0 = fmaxf((v4.x - m) * rs, 0.f);
            float o1 = fmaxf((v4.y - m) * rs, 0.f);
            float o2 = fmaxf((v4.z - m) * rs, 0.f);
            float o3 = fmaxf((v4.w - m) * rs, 0.f);
            if (top && r == 0) { o0 = o1 = o2 = o3 = 0.f; }
            if (left && q4 == 0) o0 = 0.f;
            ((float4*)&sf[b][r * 68])[q4] = make_float4(o0, o1, o2, o3);
        }
        for (int i = tid; i < 16 * 9; i += 256) {
            int o = i / 9, k = i - o * 9;
            sw[b][o * 12 + k] = w2[(obase + o) * (C1 * 9) + c1 * 9 + k];
        }
    };

    float acc0[16], acc1[16];
#pragma unroll
    for (int o = 0; o < 16; o++) { acc0[o] = 0.f; acc1[o] = 0.f; }

    stage(0, 0);
    for (int c1 = 0; c1 < C1; c1++) {
        __syncthreads();
        if (c1 + 1 < C1) stage((c1 + 1) & 1, c1 + 1);

        const float* f = sf[c1 & 1];
        const float* w = sw[c1 & 1];
        float v0[9], v1[9];
#pragma unroll
        for (int kh = 0; kh < 3; kh++) {
            const float* row = &f[(2 * ty + kh) * 68 + 2 * tx];
            float2 a0 = *(const float2*)row;
            v0[kh * 3 + 0] = a0.x; v0[kh * 3 + 1] = a0.y; v0[kh * 3 + 2] = row[2];
            float2 a1 = *(const float2*)(row + 32);
            v1[kh * 3 + 0] = a1.x; v1[kh * 3 + 1] = a1.y; v1[kh * 3 + 2] = row[34];
        }
#pragma unroll
        for (int o = 0; o < 16; o++) {
            float4 wA = *(const float4*)&w[o * 12];
            float4 wB = *(const float4*)&w[o * 12 + 4];
            float w8 = w[o * 12 + 8];
            float a0 = acc0[o], a1 = acc1[o];
            a0 += v0[0] * wA.x + v0[1] * wA.y + v0[2] * wA.z + v0[3] * wA.w
                + v0[4] * wB.x + v0[5] * wB.y + v0[6] * wB.z + v0[7] * wB.w + v0[8] * w8;
            a1 += v1[0] * wA.x + v1[1] * wA.y + v1[2] * wA.z + v1[3] * wA.w
                + v1[4] * wB.x + v1[5] * wB.y + v1[6] * wB.z + v1[7] * wB.w + v1[8] * w8;
            acc0[o] = a0; acc1[o] = a1;
        }
    }

    int oy = blockIdx.y * 16 + ty, ox = blockIdx.x * 32 + tx;
#pragma unroll
    for (int o = 0; o < 16; o++) {
        float* dst = g_nf2 + (size_t)(obase + o) * NPH * NPW + (size_t)(1 + oy) * NPW + 1;
        dst[ox]      = acc0[o];
        dst[ox + 16] = acc1[o];
    }
    int lane = tid & 31, warp = tid >> 5;
    for (int o = 0; o < 16; o++) {
        float s = acc0[o] + acc1[o];
        float q = acc0[o] * acc0[o] + acc1[o] * acc1[o];
        for (int d = 16; d; d >>= 1) {
            s += __shfl_xor_sync(~0u, s, d);
            q += __shfl_xor_sync(~0u, q, d);
        }
        if (lane == 0) { sred[warp * 16 + o] = s; qred[warp * 16 + o] = q; }
    }
    __syncthreads();
    if (tid < 16) {
        float s = 0, q = 0;
        for (int w8 = 0; w8 < 8; w8++) { s += sred[w8 * 16 + tid]; q += qred[w8 * 16 + tid]; }
        int slot = (blockIdx.y * gridDim.x + blockIdx.x) & (SLOTS - 1);
        atomicAdd(&g_sum2[(obase + tid) * SLOTS + slot], (double)s);
        atomicAdd(&g_ssq2[(obase + tid) * SLOTS + slot], (double)q);
    }
}

// ---------------- K3: conv3 from nf2 (fused bn2 staging), stats3 --------------
// grid (6,12,4), block 256; out tile 32x x 16y, 2 x-px/thread, 16 outs per z
__global__ __launch_bounds__(256, 3) void k_conv3f(const float* __restrict__ w3) {
    __shared__ __align__(16) float sf[2][33 * 68];
    __shared__ __align__(16) float sw[2][16 * 12];
    __shared__ float sm2[C2], sr2[C2];
    __shared__ float sred[8 * 16], qred[8 * 16];

    int tid = threadIdx.x, tx = tid & 15, ty = tid >> 4;
    int colbase = 64 * blockIdx.x;
    int rowbase = 32 * blockIdx.y;
    int obase = blockIdx.z * 16;
    bool left = (blockIdx.x == 0), top = (blockIdx.y == 0);

    if (tid < C2) {
        double s = 0, q = 0;
        for (int j = 0; j < SLOTS; j++) { s += g_sum2[tid * SLOTS + j]; q += g_ssq2[tid * SLOTS + j]; }
        double m = s / (double)(H2 * H2);
        double v = q / (double)(H2 * H2) - m * m;
        sm2[tid] = (float)m;
        sr2[tid] = (float)rsqrt(v + 1e-5);
    }
    __syncthreads();

    auto stage = [&](int b, int c) {
        const float* src = g_nf2 + (size_t)c * NPH * NPW;
        float m = sm2[c], rs = sr2[c];
        for (int i = tid; i < 33 * 17; i += 256) {
            int r = i / 17, q4 = i - r * 17;
            float4 v4 = *((const float4*)(src + (size_t)(rowbase + r) * NPW + colbase) + q4);
            float o0 = fmaxf((v4.x - m) * rs, 0.f);
            float o1 = fmaxf((v4.y - m) * rs, 0.f);
            float o2 = fmaxf((v4.z - m) * rs, 0.f);
            float o3 = fmaxf((v4.w - m) * rs, 0.f);
            if (top && r == 0) { o0 = o1 = o2 = o3 = 0.f; }
            if (left && q4 == 0) o0 = 0.f;
            ((float4*)&sf[b][r * 68])[q4] = make_float4(o0, o1, o2, o3);
        }
        for (int i = tid; i < 16 * 9; i += 256) {
            int o = i / 9, k = i - o * 9;
            sw[b][o * 12 + k] = w3[(obase + o) * (C2 * 9) + c * 9 + k];
        }
    };

    float acc0[16], acc1[16];
#pragma unroll
    for (int o = 0; o < 16; o++) { acc0[o] = 0.f; acc1[o] = 0.f; }

    stage(0, 0);
    for (int c = 0; c < C2; c++) {
        __syncthreads();
        if (c + 1 < C2) stage((c + 1) & 1, c + 1);

        const float* f = sf[c & 1];
        const float* w = sw[c & 1];
        float v0[9], v1[9];
#pragma unroll
        for (int kh = 0; kh < 3; kh++) {
            const float* row = &f[(2 * ty + kh) * 68 + 2 * tx];
            float2 a0 = *(const float2*)row;
            v0[kh * 3 + 0] = a0.x; v0[kh * 3 + 1] = a0.y; v0[kh * 3 + 2] = row[2];
            float2 a1 = *(const float2*)(row + 32);
            v1[kh * 3 + 0] = a1.x; v1[kh * 3 + 1] = a1.y; v1[kh * 3 + 2] = row[34];
        }
#pragma unroll
        for (int o = 0; o < 16; o++) {
            float4 wA = *(const float4*)&w[o * 12];
            float4 wB = *(const float4*)&w[o * 12 + 4];
            float w8 = w[o * 12 + 8];
            float a0 = acc0[o], a1 = acc1[o];
            a0 += v0[0] * wA.x + v0[1] * wA.y + v0[2] * wA.z + v0[3] * wA.w
                + v0[4] * wB.x + v0[5] * wB.y + v0[6] * wB.z + v0[7] * wB.w + v0[8] * w8;
            a1 += v1[0] * wA.x + v1[1] * wA.y + v1[2] * wA.z + v1[3] * wA.w
                + v1[4] * wB.x + v1[5] * wB.y + v1[6] * wB.z + v1[7] * wB.w + v1[8] * w8;
            acc0[o] = a0; acc1[o] = a1;
        }
    }

    int oy = blockIdx.y * 16 + ty, ox = blockIdx.x * 32 + tx;
#pragma unroll
    for (int o = 0; o < 16; o++) {
        g_f3[(size_t)(obase + o) * H3 * H3 + (size_t)oy * H3 + ox]      = acc0[o];
        g_f3[(size_t)(obase + o) * H3 * H3 + (size_t)oy * H3 + ox + 16] = acc1[o];
    }

    int lane = tid & 31, warp = tid >> 5;
    for (int o = 0; o < 16; o++) {
        float s = acc0[o] + acc1[o];
        float q = acc0[o] * acc0[o] + acc1[o] * acc1[o];
        for (int d = 16; d; d >>= 1) {
            s += __shfl_xor_sync(~0u, s, d);
            q += __shfl_xor_sync(~0u, q, d);
        }
        if (lane == 0) { sred[warp * 16 + o] = s; qred[warp * 16 + o] = q; }
    }
    __syncthreads();
    if (tid < 16) {
        float s = 0, q = 0;
        for (int w8 = 0; w8 < 8; w8++) { s += sred[w8 * 16 + tid]; q += qred[w8 * 16 + tid]; }
        int slot = ((blockIdx.z * gridDim.y + blockIdx.y) * gridDim.x + blockIdx.x) & (SLOTS - 1);
        atomicAdd(&g_sum3[(obase + tid) * SLOTS + slot], (double)s);
        atomicAdd(&g_ssq3[(obase + tid) * SLOTS + slot], (double)q);
    }
}

// ---------------- heads: partial dot-products, 8-channel groups ----------------
__global__ __launch_bounds__(256) void k_heads_acc(
    const float* __restrict__ pw, const float* __restrict__ tw,
    const float* __restrict__ shw, const float* __restrict__ scw,
    const float* __restrict__ tiw) {
    int cg = blockIdx.y;
    __shared__ float sm3[8], sr3[8];
    int tid = threadIdx.x;
    if (tid < 8) {
        int c = cg * 8 + tid;
        double s = 0, q = 0;
        for (int j = 0; j < SLOTS; j++) { s += g_sum3[c * SLOTS + j]; q += g_ssq3[c * SLOTS + j]; }
        double m = s / (double)(H3 * H3);
        double v = q / (double)(H3 * H3) - m * m;
        sm3[tid] = (float)m;
        sr3[tid] = (float)rsqrt(v + 1e-5);
    }
    __syncthreads();

    int p = blockIdx.x * 256 + tid;
    int gx = p % NG, gy = p / NG;

    float ap = 0, at = 0, as0 = 0, as1 = 0, asc = 0, ati = 0;
#pragma unroll
    for (int cc = 0; cc < 8; cc++) {
        int c = cg * 8 + cc;
        float m = sm3[cc], r = sr3[cc];
        const float* fc = g_f3 + (size_t)c * H3 * H3 + (size_t)(2 * gy) * H3 + 2 * gx;
#pragma unroll
        for (int kh = 0; kh < 2; kh++)
#pragma unroll
            for (int kw = 0; kw < 2; kw++) {
                float v = fmaxf((fc[kh * H3 + kw] - m) * r, 0.f);
                int wi = c * 4 + kh * 2 + kw;
                ap  += v * pw[wi];
                at  += v * tw[wi];
                as0 += v * shw[wi];
                as1 += v * shw[256 + wi];
                asc += v * scw[wi];
                ati += v * tiw[wi];
            }
    }
    float* part = g_hpart[cg];
    part[0 * NPATCH + p] = ap;
    part[1 * NPATCH + p] = at;
    part[2 * NPATCH + p] = as0;
    part[3 * NPATCH + p] = as1;
    part[4 * NPATCH + p] = asc;
    part[5 * NPATCH + p] = ati;
}

__global__ __launch_bounds__(256) void k_heads_fin(
    const float* __restrict__ pb, const float* __restrict__ tb,
    const float* __restrict__ shb, const float* __restrict__ scb,
    const float* __restrict__ tib) {
    int p = blockIdx.x * 256 + threadIdx.x;
    float a[6] = {0, 0, 0, 0, 0, 0};
#pragma unroll
    for (int g = 0; g < 8; g++)
#pragma unroll
        for (int j = 0; j < 6; j++) a[j] += g_hpart[g][j * NPATCH + p];

    float psi = 3.14159f * tanhf(a[0] + pb[0]);
    float th  = 3.14159f * tanhf(a[1] + tb[0]);
    float s0  = 0.2f * tanhf(a[2] + shb[0]);
    float s1  = 0.2f * tanhf(a[3] + shb[1]);
    float sc  = fminf(fmaxf(1.f + 0.25f * tanhf(a[4] + scb[0]), 0.8f), 1.25f);
    float ti  = fminf(fmaxf(1.f + 0.8f  * tanhf(a[5] + tib[0]), 1.0f), 1.8f);

    float cp = cosf(psi), sp = sinf(psi);
    float ct = cosf(th),  st = sinf(th);
    float M00 = ti * ct, M01 = -ti * st;
    float M10 = st / ti, M11 = ct / ti;
    g_A[p * 4 + 0] = sc * (cp * M00 - sp * M10);
    g_A[p * 4 + 1] = sc * (cp * M01 - sp * M11);
    g_A[p * 4 + 2] = sc * (sp * M00 + cp * M10);
    g_A[p * 4 + 3] = sc * (sp * M01 + cp * M11);
    g_shift[p]          = s0;
    g_shift[NPATCH + p] = s1;
}

// ---------------- assemble (shift cross-channel reindex) + aff ----------------
__global__ void k_assemble(float* __restrict__ out) {
    int n = blockIdx.x * blockDim.x + threadIdx.x;
    if (n >= NPATCH) return;
    float t0 = g_A[n * 4 + 0], t1 = g_A[n * 4 + 1];
    float t3 = g_A[n * 4 + 2], t4 = g_A[n * 4 + 3];
    float t2 = g_shift[2 * n];
    float t5 = g_shift[2 * n + 1];
    g_trans[n * 6 + 0] = t0; g_trans[n * 6 + 1] = t1; g_trans[n * 6 + 2] = t2;
    g_trans[n * 6 + 3] = t3; g_trans[n * 6 + 4] = t4; g_trans[n * 6 + 5] = t5;

    float cx = 4.f + 8.f * (float)(n % NG);
    float cy = 4.f + 8.f * (float)(n / NG);
    float* a = out + (size_t)NPATCH * 1024 + (size_t)n * 6;
    a[0] = 32.f * t0; a[1] = 32.f * t1; a[2] = cx + 32.f * t2;
    a[3] = 32.f * t3; a[4] = 32.f * t4; a[5] = cy + 32.f * t5;
}

// ---------------- bilinear sampler: 256 thr, 4 px/thread, float4 store ----------------
__global__ __launch_bounds__(256) void k_sample(const float* __restrict__ img,
                                                float* __restrict__ out) {
    int n = blockIdx.x;
    __shared__ float t[6];
    if (threadIdx.x < 6) t[threadIdx.x] = g_trans[n * 6 + threadIdx.x];
    __syncthreads();
    float t0 = t[0], t1 = t[1], t2 = t[2], t3 = t[3], t4 = t[4], t5 = t[5];

    int p4 = threadIdx.x * 4;
    int h = p4 >> 5, w0 = p4 & 31;
    float Y = ((float)h + 0.5f) * (2.f / 32.f) - 1.f;
    int bx = (n % NG) * 8 - PADO;
    int by = (n / NG) * 8 - PADO;

    auto g = [&](int yy, int xx) -> float {
        if ((unsigned)yy >= GPS || (unsigned)xx >= GPS) return 0.f;
        int ir = by + yy, ic = bx + xx;
        if ((unsigned)ir >= HW || (unsigned)ic >= HW) return 0.f;
        return img[(size_t)ir * HW + ic];
    };

    float res[4];
#pragma unroll
    for (int e = 0; e < 4; e++) {
        float X = ((float)(w0 + e) + 0.5f) * (2.f / 32.f) - 1.f;
        float gx = (X * t0 + Y * t1 + t2) / 4.5f;
        float gy = (X * t3 + Y * t4 + t5) / 4.5f;
        float ix = ((gx + 1.f) * 144.f - 1.f) * 0.5f;
        float iy = ((gy + 1.f) * 144.f - 1.f) * 0.5f;
        float x0f = floorf(ix), y0f = floorf(iy);
        float wx = ix - x0f, wy = iy - y0f;
        int x0 = (int)x0f, y0 = (int)y0f;
        res[e] = (1.f - wy) * ((1.f - wx) * g(y0, x0)     + wx * g(y0, x0 + 1)) +
                 wy        * ((1.f - wx) * g(y0 + 1, x0) + wx * g(y0 + 1, x0 + 1));
    }
    *(float4*)(out + (size_t)n * 1024 + p4) = make_float4(res[0], res[1], res[2], res[3]);
}

// ---------------- launch ----------------
extern "C" void kernel_launch(void* const* d_in, const int* in_sizes, int n_in,
                              void* d_out, int out_size) {
    const float* img = (const float*)d_in[0];
    const float* w1  = (const float*)d_in[1];
    const float* w2  = (const float*)d_in[2];
    const float* w3  = (const float*)d_in[3];
    const float* pw  = (const float*)d_in[4];
    const float* pb  = (const float*)d_in[5];
    const float* tw  = (const float*)d_in[6];
    const float* tb  = (const float*)d_in[7];
    const float* shw = (const float*)d_in[8];
    const float* shb = (const float*)d_in[9];
    const float* scw = (const float*)d_in[10];
    const float* scb = (const float*)d_in[11];
    const float* tiw = (const float*)d_in[12];
    const float* tib = (const float*)d_in[13];
    float* out = (float*)d_out;

    k_zero_stats<<<1, 1024>>>();
    k_conv1s<<<dim3(24, 24), 256>>>(img, w1);
    k_conv2f<<<dim3(12, 24, 2), 256>>>(w2);
    k_conv3f<<<dim3(6, 12, 4), 256>>>(w3);
    k_heads_acc<<<dim3(36, 8), 256>>>(pw, tw, shw, scw, tiw);
    k_heads_fin<<<36, 256>>>(pb, tb, shb, scb, tib);
    k_assemble<<<36, 256>>>(out);
    k_sample<<<NPATCH, 256>>>(img, out);
}